// round 7
// baseline (speedup 1.0000x reference)
#include <cuda_runtime.h>
#include <cuda_bf16.h>
#include <math.h>
#include <stdint.h>

// Problem constants
#define BATCH 4
#define SEQ 2048
#define DMODEL 1024
#define NHEADS 16
#define HDIM 64
#define MTOT (BATCH * SEQ)          // 8192 rows

// ---------------------------------------------------------------------------
// Scratch (device globals: allocation-free, graph-safe)
// ---------------------------------------------------------------------------
__device__ float g_q[MTOT * DMODEL];
__device__ float g_k[MTOT * DMODEL];
__device__ float g_v[MTOT * DMODEL];
__device__ float g_attn[MTOT * DMODEL];
__device__ float g_xr[MTOT * DMODEL];            // tf32-rounded x
__device__ float g_wr[4][DMODEL * DMODEL];       // tf32-rounded Wq,Wk,Wv,Wo

// ---------------------------------------------------------------------------
// Helpers
// ---------------------------------------------------------------------------
__device__ __forceinline__ uint32_t smem_to_u32(const void* p) {
    uint32_t a;
    asm("{ .reg .u64 t; cvta.to.shared.u64 t, %1; cvt.u32.u64 %0, t; }"
        : "=r"(a) : "l"(p));
    return a;
}
__device__ __forceinline__ void cp_async16(uint32_t dst, const void* src) {
    asm volatile("cp.async.cg.shared.global [%0], [%1], 16;" :: "r"(dst), "l"(src));
}
#define CP_COMMIT() asm volatile("cp.async.commit_group;" ::: "memory")
#define CP_WAIT0()  asm volatile("cp.async.wait_group 0;" ::: "memory")
#define CP_WAIT2()  asm volatile("cp.async.wait_group 2;" ::: "memory")

__device__ __forceinline__ uint32_t f2tf32(float f) {
    uint32_t r;
    asm("cvt.rna.tf32.f32 %0, %1;" : "=r"(r) : "f"(f));
    return r;
}
__device__ __forceinline__ float roundtf(float f) {
    return __uint_as_float(f2tf32(f));
}
__device__ __forceinline__ void mma_tf32(float* c, const uint32_t* a, const uint32_t* b) {
    asm volatile(
        "mma.sync.aligned.m16n8k8.row.col.f32.tf32.tf32.f32 "
        "{%0,%1,%2,%3}, {%4,%5,%6,%7}, {%8,%9}, {%0,%1,%2,%3};"
        : "+f"(c[0]), "+f"(c[1]), "+f"(c[2]), "+f"(c[3])
        : "r"(a[0]), "r"(a[1]), "r"(a[2]), "r"(a[3]), "r"(b[0]), "r"(b[1]));
}

// ---------------------------------------------------------------------------
// Pre-pass: round fp32 -> tf32 bit pattern (vectorized)
// ---------------------------------------------------------------------------
__global__ __launch_bounds__(256)
void round_tf32_kernel(const float4* __restrict__ in, float4* __restrict__ out, int n4)
{
    int i = blockIdx.x * 256 + threadIdx.x;
    if (i < n4) {
        float4 v = in[i];
        v.x = roundtf(v.x);
        v.y = roundtf(v.y);
        v.z = roundtf(v.z);
        v.w = roundtf(v.w);
        out[i] = v;
    }
}

// ---------------------------------------------------------------------------
// tf32 mma.sync GEMM core (BM=128 BN=128 BK=16, 256 thr, 3-stage cp.async).
// Inputs MUST be pre-rounded to tf32 bit patterns — no cvt in inner loop.
// ---------------------------------------------------------------------------
#define GKDIM 1024
#define GNDIM 1024
#define NKT 64
#define A_STRIDE 20
#define B_STRIDE 136
#define A_BYTES (128 * A_STRIDE * 4)
#define B_BYTES (16 * B_STRIDE * 4)
#define STAGE_BYTES (A_BYTES + B_BYTES)
#define GSTAGES 3
#define GEMM_SMEM (GSTAGES * STAGE_BYTES)

__device__ __forceinline__ void gemm_core(const float* __restrict__ A,
                                          const float* __restrict__ B,
                                          const float* __restrict__ bias,
                                          float* __restrict__ C,
                                          int m0, int n0, int useBias, int roundOut,
                                          char* dsmem)
{
    const int tid = threadIdx.x;
    const int wid = tid >> 5;
    const int lane = tid & 31;
    const int wm0 = (wid & 3) * 32;
    const int wn0 = (wid >> 2) * 64;
    const int qr = lane >> 2;
    const int qc = lane & 3;

    const uint32_t sbase = smem_to_u32(dsmem);

    float acc[2][8][4];
#pragma unroll
    for (int i = 0; i < 2; i++)
#pragma unroll
        for (int j = 0; j < 8; j++)
#pragma unroll
            for (int l = 0; l < 4; l++) acc[i][j][l] = 0.f;

    auto issue_stage = [&](int stage, int k0) {
        uint32_t aB = sbase + stage * STAGE_BYTES;
        uint32_t bB = aB + A_BYTES;
#pragma unroll
        for (int i = 0; i < 2; i++) {
            int idx = tid * 2 + i;
            int row = idx >> 2;
            int c4 = idx & 3;
            cp_async16(aB + row * (A_STRIDE * 4) + c4 * 16,
                       A + (size_t)(m0 + row) * GKDIM + k0 + c4 * 4);
            int krow = idx >> 5;
            int col = idx & 31;
            cp_async16(bB + krow * (B_STRIDE * 4) + col * 16,
                       B + (size_t)(k0 + krow) * GNDIM + n0 + col * 4);
        }
    };

    issue_stage(0, 0);
    CP_COMMIT();
    issue_stage(1, 16);
    CP_COMMIT();

    for (int kt = 0; kt < NKT; kt++) {
        int lt = kt + 2;
        if (lt < NKT) issue_stage(lt % GSTAGES, lt * 16);
        CP_COMMIT();
        CP_WAIT2();
        __syncthreads();

        const uint32_t* As = (const uint32_t*)(dsmem + (kt % GSTAGES) * STAGE_BYTES);
        const uint32_t* Bs = (const uint32_t*)(dsmem + (kt % GSTAGES) * STAGE_BYTES + A_BYTES);

#pragma unroll
        for (int ks = 0; ks < 2; ks++) {
            const int kb = ks * 8;
            uint32_t afr[2][4];
            uint32_t bfr[8][2];
#pragma unroll
            for (int mt = 0; mt < 2; mt++) {
                int mbase = wm0 + mt * 16;
                afr[mt][0] = As[(mbase + qr) * A_STRIDE + kb + qc];
                afr[mt][1] = As[(mbase + qr + 8) * A_STRIDE + kb + qc];
                afr[mt][2] = As[(mbase + qr) * A_STRIDE + kb + qc + 4];
                afr[mt][3] = As[(mbase + qr + 8) * A_STRIDE + kb + qc + 4];
            }
#pragma unroll
            for (int nt = 0; nt < 8; nt++) {
                int nc = wn0 + nt * 8 + qr;
                bfr[nt][0] = Bs[(kb + qc) * B_STRIDE + nc];
                bfr[nt][1] = Bs[(kb + qc + 4) * B_STRIDE + nc];
            }
#pragma unroll
            for (int mt = 0; mt < 2; mt++)
#pragma unroll
                for (int nt = 0; nt < 8; nt++)
                    mma_tf32(acc[mt][nt], afr[mt], bfr[nt]);
        }
        __syncthreads();
    }

#pragma unroll
    for (int mt = 0; mt < 2; mt++) {
        int r0 = m0 + wm0 + mt * 16 + qr;
#pragma unroll
        for (int nt = 0; nt < 8; nt++) {
            int col = n0 + wn0 + nt * 8 + 2 * qc;
            float bx = 0.f, by = 0.f;
            if (useBias) {
                float2 bb = *(const float2*)(bias + col);
                bx = bb.x; by = bb.y;
            }
            float2 v0 = {acc[mt][nt][0] + bx, acc[mt][nt][1] + by};
            float2 v1 = {acc[mt][nt][2] + bx, acc[mt][nt][3] + by};
            if (roundOut) {
                v0.x = roundtf(v0.x); v0.y = roundtf(v0.y);
                v1.x = roundtf(v1.x); v1.y = roundtf(v1.y);
            }
            *(float2*)(C + (size_t)r0 * GNDIM + col) = v0;
            *(float2*)(C + (size_t)(r0 + 8) * GNDIM + col) = v1;
        }
    }
}

// Fused QKV: grid.x = 24 (3 weights x 8 N-tiles), grid.y = 64 (M-tiles)
__global__ __launch_bounds__(256)
void gemm_qkv_kernel(const float* __restrict__ x,
                     const float* __restrict__ Wq, const float* __restrict__ Wk,
                     const float* __restrict__ Wv,
                     float* __restrict__ q, float* __restrict__ k,
                     float* __restrict__ v)
{
    extern __shared__ char dsmem[];
    const int sel = blockIdx.x >> 3;
    const int n0 = (blockIdx.x & 7) * 128;
    const int m0 = blockIdx.y * 128;
    const float* B = (sel == 0) ? Wq : (sel == 1) ? Wk : Wv;
    float* C = (sel == 0) ? q : (sel == 1) ? k : v;
    gemm_core(x, B, nullptr, C, m0, n0, 0, 1, dsmem);   // round outputs
}

__global__ __launch_bounds__(256)
void gemm_tc_kernel(const float* __restrict__ A, const float* __restrict__ B,
                    const float* __restrict__ bias, float* __restrict__ C,
                    int useBias)
{
    extern __shared__ char dsmem[];
    gemm_core(A, B, bias, C, blockIdx.y * 128, blockIdx.x * 128, useBias, 0, dsmem);
}

// ---------------------------------------------------------------------------
// Flash attention (causal) with tf32 mma.sync. Inputs pre-rounded.
// Br=128, Bc=64, 256 threads (8 warps). Single-buffered K/V (2 CTA/SM).
// ---------------------------------------------------------------------------
struct AttnSmem {
    float Qs[128][68];
    float Ks[64][68];
    float Vs[64][72];
    float Ps[128][68];
    float red_max[2][128];
    float red_sum[2][128];
    float row_scale[128];
    float row_inv[128];
};   // ~106 KB

__global__ __launch_bounds__(256, 2)
void attn_mma_kernel(const float* __restrict__ q, const float* __restrict__ k,
                     const float* __restrict__ v, float* __restrict__ out)
{
    extern __shared__ char smem_raw[];
    AttnSmem& sm = *reinterpret_cast<AttnSmem*>(smem_raw);

    const int tid = threadIdx.x;
    const int wid = tid >> 5;
    const int lane = tid & 31;
    const int qr = lane >> 2;        // 0..7
    const int qc = lane & 3;         // 0..3
    const int q0 = (gridDim.x - 1 - blockIdx.x) * 128;   // heavy tiles first
    const int bh = blockIdx.y;
    const int b = bh >> 4;
    const int h = bh & 15;

    const size_t base = (size_t)b * SEQ * DMODEL + (size_t)h * HDIM;

    // Load Q tile, pre-scaled by 1/sqrt(Dh)=0.125 (power of 2: stays tf32-exact)
    for (int idx = tid; idx < 2048; idx += 256) {
        int r = idx >> 4;
        int d4 = (idx & 15) << 2;
        float4 val = *(const float4*)(q + base + (size_t)(q0 + r) * DMODEL + d4);
        sm.Qs[r][d4 + 0] = val.x * 0.125f;
        sm.Qs[r][d4 + 1] = val.y * 0.125f;
        sm.Qs[r][d4 + 2] = val.z * 0.125f;
        sm.Qs[r][d4 + 3] = val.w * 0.125f;
    }

    auto load_k = [&](int k0) {
#pragma unroll
        for (int i = 0; i < 4; i++) {
            int idx = tid + i * 256;
            int c = idx >> 4;
            int d4 = (idx & 15) << 2;
            cp_async16(smem_to_u32(&sm.Ks[c][d4]),
                       k + base + (size_t)(k0 + c) * DMODEL + d4);
        }
    };
    auto load_v = [&](int k0) {
#pragma unroll
        for (int i = 0; i < 4; i++) {
            int idx = tid + i * 256;
            int c = idx >> 4;
            int d4 = (idx & 15) << 2;
            cp_async16(smem_to_u32(&sm.Vs[c][d4]),
                       v + base + (size_t)(k0 + c) * DMODEL + d4);
        }
    };

    const int srow = tid >> 1;
    const int shalf = tid & 1;
    const int sc0 = shalf * 32;
    float m_i = -INFINITY;
    float l_i = 0.f;

    float oacc[8][4];
#pragma unroll
    for (int nt = 0; nt < 8; nt++)
#pragma unroll
        for (int l = 0; l < 4; l++) oacc[nt][l] = 0.f;

    const int wm = (wid & 3) * 32;
    const int wn = (wid >> 2) * 32;

    const int nkt = (q0 >> 6) + 2;

    load_k(0);
    CP_COMMIT();

    for (int kt = 0; kt < nkt; kt++) {
        const int k0 = kt * 64;

        load_v(k0);
        CP_COMMIT();
        CP_WAIT0();
        __syncthreads();

        // ---- S = Q @ K^T (warp tile 32x32), no cvt: data pre-rounded ----
        float sacc[2][4][4];
#pragma unroll
        for (int mt = 0; mt < 2; mt++)
#pragma unroll
            for (int nt = 0; nt < 4; nt++)
#pragma unroll
                for (int l = 0; l < 4; l++) sacc[mt][nt][l] = 0.f;

        const uint32_t* Qu = (const uint32_t*)&sm.Qs[0][0];
        const uint32_t* Ku = (const uint32_t*)&sm.Ks[0][0];
        const uint32_t* Vu = (const uint32_t*)&sm.Vs[0][0];
        const uint32_t* Pu = (const uint32_t*)&sm.Ps[0][0];

#pragma unroll
        for (int ks = 0; ks < 8; ks++) {
            const int kb = ks * 8;
            uint32_t afr[2][4];
            uint32_t bfr[4][2];
#pragma unroll
            for (int mt = 0; mt < 2; mt++) {
                int mbase = wm + mt * 16;
                afr[mt][0] = Qu[(mbase + qr) * 68 + kb + qc];
                afr[mt][1] = Qu[(mbase + qr + 8) * 68 + kb + qc];
                afr[mt][2] = Qu[(mbase + qr) * 68 + kb + qc + 4];
                afr[mt][3] = Qu[(mbase + qr + 8) * 68 + kb + qc + 4];
            }
#pragma unroll
            for (int nt = 0; nt < 4; nt++) {
                int nc = wn + nt * 8 + qr;
                bfr[nt][0] = Ku[nc * 68 + kb + qc];
                bfr[nt][1] = Ku[nc * 68 + kb + qc + 4];
            }
#pragma unroll
            for (int mt = 0; mt < 2; mt++)
#pragma unroll
                for (int nt = 0; nt < 4; nt++)
                    mma_tf32(sacc[mt][nt], afr[mt], bfr[nt]);
        }

        // Write S fragments to Ps
#pragma unroll
        for (int mt = 0; mt < 2; mt++) {
            int r0 = wm + mt * 16 + qr;
#pragma unroll
            for (int nt = 0; nt < 4; nt++) {
                int col = wn + nt * 8 + 2 * qc;
                *(float2*)&sm.Ps[r0][col]     = make_float2(sacc[mt][nt][0], sacc[mt][nt][1]);
                *(float2*)&sm.Ps[r0 + 8][col] = make_float2(sacc[mt][nt][2], sacc[mt][nt][3]);
            }
        }
        __syncthreads();

        // Prefetch K(kt+1) — overlaps softmax + PV
        if (kt + 1 < nkt) {
            load_k(k0 + 64);
            CP_COMMIT();
        }

        // ---- Online softmax (writes pre-rounded exp values) ----
        {
            const int climit = q0 + srow - k0;
            const bool nomask = (climit >= sc0 + 31);
            float mloc = -INFINITY;
            if (nomask) {
#pragma unroll
                for (int c4 = 0; c4 < 8; c4++) {
                    float4 vv = *(const float4*)&sm.Ps[srow][sc0 + c4 * 4];
                    mloc = fmaxf(mloc, fmaxf(fmaxf(vv.x, vv.y), fmaxf(vv.z, vv.w)));
                }
            } else {
#pragma unroll
                for (int c4 = 0; c4 < 8; c4++) {
                    float4 vv = *(const float4*)&sm.Ps[srow][sc0 + c4 * 4];
                    int c = sc0 + c4 * 4;
                    if (c + 0 <= climit) mloc = fmaxf(mloc, vv.x);
                    if (c + 1 <= climit) mloc = fmaxf(mloc, vv.y);
                    if (c + 2 <= climit) mloc = fmaxf(mloc, vv.z);
                    if (c + 3 <= climit) mloc = fmaxf(mloc, vv.w);
                }
            }
            sm.red_max[shalf][srow] = mloc;
            __syncthreads();
            float mtile = fmaxf(sm.red_max[0][srow], sm.red_max[1][srow]);
            float mnew = fmaxf(m_i, mtile);
            float rs = __expf(m_i - mnew);
            if (shalf == 0) sm.row_scale[srow] = rs;

            float lsum = 0.f;
            if (nomask) {
#pragma unroll
                for (int c4 = 0; c4 < 8; c4++) {
                    float4 vv = *(float4*)&sm.Ps[srow][sc0 + c4 * 4];
                    vv.x = __expf(vv.x - mnew);
                    vv.y = __expf(vv.y - mnew);
                    vv.z = __expf(vv.z - mnew);
                    vv.w = __expf(vv.w - mnew);
                    lsum += vv.x + vv.y + vv.z + vv.w;
                    vv.x = roundtf(vv.x); vv.y = roundtf(vv.y);
                    vv.z = roundtf(vv.z); vv.w = roundtf(vv.w);
                    *(float4*)&sm.Ps[srow][sc0 + c4 * 4] = vv;
                }
            } else {
#pragma unroll
                for (int c4 = 0; c4 < 8; c4++) {
                    float4 vv = *(float4*)&sm.Ps[srow][sc0 + c4 * 4];
                    int c = sc0 + c4 * 4;
                    vv.x = (c + 0 <= climit) ? __expf(vv.x - mnew) : 0.f;
                    vv.y = (c + 1 <= climit) ? __expf(vv.y - mnew) : 0.f;
                    vv.z = (c + 2 <= climit) ? __expf(vv.z - mnew) : 0.f;
                    vv.w = (c + 3 <= climit) ? __expf(vv.w - mnew) : 0.f;
                    lsum += vv.x + vv.y + vv.z + vv.w;
                    vv.x = roundtf(vv.x); vv.y = roundtf(vv.y);
                    vv.z = roundtf(vv.z); vv.w = roundtf(vv.w);
                    *(float4*)&sm.Ps[srow][sc0 + c4 * 4] = vv;
                }
            }
            sm.red_sum[shalf][srow] = lsum;
            __syncthreads();
            l_i = l_i * rs + sm.red_sum[0][srow] + sm.red_sum[1][srow];
            m_i = mnew;
        }

        // ---- O = O*rs + P @ V (warp tile 16x64), no cvt ----
        {
            const int mbase = wid * 16;
            float rs0 = sm.row_scale[mbase + qr];
            float rs1 = sm.row_scale[mbase + qr + 8];
#pragma unroll
            for (int nt = 0; nt < 8; nt++) {
                oacc[nt][0] *= rs0; oacc[nt][1] *= rs0;
                oacc[nt][2] *= rs1; oacc[nt][3] *= rs1;
            }
#pragma unroll
            for (int ks = 0; ks < 8; ks++) {
                const int kb = ks * 8;
                uint32_t afr[4];
                afr[0] = Pu[(mbase + qr) * 68 + kb + qc];
                afr[1] = Pu[(mbase + qr + 8) * 68 + kb + qc];
                afr[2] = Pu[(mbase + qr) * 68 + kb + qc + 4];
                afr[3] = Pu[(mbase + qr + 8) * 68 + kb + qc + 4];
                uint32_t bfr[8][2];
#pragma unroll
                for (int nt = 0; nt < 8; nt++) {
                    int nc = nt * 8 + qr;
                    bfr[nt][0] = Vu[(kb + qc) * 72 + nc];
                    bfr[nt][1] = Vu[(kb + qc + 4) * 72 + nc];
                }
#pragma unroll
                for (int nt = 0; nt < 8; nt++)
                    mma_tf32(oacc[nt], afr, bfr[nt]);
            }
        }
        __syncthreads();
    }

    // Final normalization (pre-round for O-projection input)
    if (shalf == 0) sm.row_inv[srow] = 1.f / l_i;
    __syncthreads();

    {
        const int mbase = wid * 16;
        float inv0 = sm.row_inv[mbase + qr];
        float inv1 = sm.row_inv[mbase + qr + 8];
        size_t r0 = base + (size_t)(q0 + mbase + qr) * DMODEL;
        size_t r1 = base + (size_t)(q0 + mbase + qr + 8) * DMODEL;
#pragma unroll
        for (int nt = 0; nt < 8; nt++) {
            int col = nt * 8 + 2 * qc;
            *(float2*)(out + r0 + col) =
                make_float2(roundtf(oacc[nt][0] * inv0), roundtf(oacc[nt][1] * inv0));
            *(float2*)(out + r1 + col) =
                make_float2(roundtf(oacc[nt][2] * inv1), roundtf(oacc[nt][3] * inv1));
        }
    }
}

// ---------------------------------------------------------------------------
// Launch
// ---------------------------------------------------------------------------
extern "C" void kernel_launch(void* const* d_in, const int* in_sizes, int n_in,
                              void* d_out, int out_size)
{
    const float* x  = (const float*)d_in[0];
    const float* Wq = (const float*)d_in[1];
    const float* Wk = (const float*)d_in[2];
    const float* Wv = (const float*)d_in[3];
    const float* Wo = (const float*)d_in[4];
    const float* bo = (const float*)d_in[5];
    float* out = (float*)d_out;

    float *qp, *kp, *vp, *ap, *xr, *wr;
    cudaGetSymbolAddress((void**)&qp, g_q);
    cudaGetSymbolAddress((void**)&kp, g_k);
    cudaGetSymbolAddress((void**)&vp, g_v);
    cudaGetSymbolAddress((void**)&ap, g_attn);
    cudaGetSymbolAddress((void**)&xr, g_xr);
    cudaGetSymbolAddress((void**)&wr, g_wr);
    float* wrq = wr;
    float* wrk = wr + 1 * DMODEL * DMODEL;
    float* wrv = wr + 2 * DMODEL * DMODEL;
    float* wro = wr + 3 * DMODEL * DMODEL;

    cudaFuncSetAttribute(gemm_qkv_kernel, cudaFuncAttributeMaxDynamicSharedMemorySize, GEMM_SMEM);
    cudaFuncSetAttribute(gemm_tc_kernel, cudaFuncAttributeMaxDynamicSharedMemorySize, GEMM_SMEM);
    cudaFuncSetAttribute(attn_mma_kernel, cudaFuncAttributeMaxDynamicSharedMemorySize,
                         (int)sizeof(AttnSmem));

    // Pre-round inputs to tf32 bit patterns
    const int XN4 = MTOT * DMODEL / 4;       // 2097152
    const int WN4 = DMODEL * DMODEL / 4;     // 262144
    round_tf32_kernel<<<(XN4 + 255) / 256, 256>>>((const float4*)x, (float4*)xr, XN4);
    round_tf32_kernel<<<(WN4 + 255) / 256, 256>>>((const float4*)Wq, (float4*)wrq, WN4);
    round_tf32_kernel<<<(WN4 + 255) / 256, 256>>>((const float4*)Wk, (float4*)wrk, WN4);
    round_tf32_kernel<<<(WN4 + 255) / 256, 256>>>((const float4*)Wv, (float4*)wrv, WN4);
    round_tf32_kernel<<<(WN4 + 255) / 256, 256>>>((const float4*)Wo, (float4*)wro, WN4);

    // Fused QKV projections (write pre-rounded q,k,v)
    dim3 qkvgrid(24, MTOT / 128);
    gemm_qkv_kernel<<<qkvgrid, 256, GEMM_SMEM>>>(xr, wrq, wrk, wrv, qp, kp, vp);

    // Causal flash attention (writes pre-rounded attn output)
    dim3 agrid(SEQ / 128, BATCH * NHEADS);
    attn_mma_kernel<<<agrid, 256, sizeof(AttnSmem)>>>(qp, kp, vp, ap);

    // Output projection + bias (full fp32 output)
    dim3 ggrid(GNDIM / 128, MTOT / 128);
    gemm_tc_kernel<<<ggrid, 256, GEMM_SMEM>>>(ap, wro, bo, out, 1);
}

// round 8
// speedup vs baseline: 1.4711x; 1.4711x over previous
#include <cuda_runtime.h>
#include <cuda_bf16.h>
#include <math.h>
#include <stdint.h>

// Problem constants
#define BATCH 4
#define SEQ 2048
#define DMODEL 1024
#define NHEADS 16
#define HDIM 64
#define MTOT (BATCH * SEQ)          // 8192 rows

// ---------------------------------------------------------------------------
// Scratch (device globals: allocation-free, graph-safe)
// ---------------------------------------------------------------------------
__device__ float g_q[MTOT * DMODEL];
__device__ float g_k[MTOT * DMODEL];
__device__ float g_v[MTOT * DMODEL];
__device__ float g_attn[MTOT * DMODEL];
__device__ float g_wr[4][DMODEL * DMODEL];   // tf32-rounded Wq,Wk,Wv,Wo

// ---------------------------------------------------------------------------
// Helpers
// ---------------------------------------------------------------------------
__device__ __forceinline__ uint32_t smem_to_u32(const void* p) {
    uint32_t a;
    asm("{ .reg .u64 t; cvta.to.shared.u64 t, %1; cvt.u32.u64 %0, t; }"
        : "=r"(a) : "l"(p));
    return a;
}
__device__ __forceinline__ void cp_async16(uint32_t dst, const void* src) {
    asm volatile("cp.async.cg.shared.global [%0], [%1], 16;" :: "r"(dst), "l"(src));
}
#define CP_COMMIT() asm volatile("cp.async.commit_group;" ::: "memory")
#define CP_WAIT0()  asm volatile("cp.async.wait_group 0;" ::: "memory")
#define CP_WAIT2()  asm volatile("cp.async.wait_group 2;" ::: "memory")

__device__ __forceinline__ uint32_t f2tf32(float f) {
    uint32_t r;
    asm("cvt.rna.tf32.f32 %0, %1;" : "=r"(r) : "f"(f));
    return r;
}
__device__ __forceinline__ float roundtf(float f) {
    return __uint_as_float(f2tf32(f));
}
__device__ __forceinline__ void mma_tf32(float* c, const uint32_t* a, const uint32_t* b) {
    asm volatile(
        "mma.sync.aligned.m16n8k8.row.col.f32.tf32.tf32.f32 "
        "{%0,%1,%2,%3}, {%4,%5,%6,%7}, {%8,%9}, {%0,%1,%2,%3};"
        : "+f"(c[0]), "+f"(c[1]), "+f"(c[2]), "+f"(c[3])
        : "r"(a[0]), "r"(a[1]), "r"(a[2]), "r"(a[3]), "r"(b[0]), "r"(b[1]));
}

// ---------------------------------------------------------------------------
// Pre-pass: round fp32 -> tf32 bit pattern (weights only, 1M elems each)
// ---------------------------------------------------------------------------
__global__ __launch_bounds__(256)
void round_tf32_kernel(const float4* __restrict__ in, float4* __restrict__ out, int n4)
{
    int i = blockIdx.x * 256 + threadIdx.x;
    if (i < n4) {
        float4 v = in[i];
        v.x = roundtf(v.x);
        v.y = roundtf(v.y);
        v.z = roundtf(v.z);
        v.w = roundtf(v.w);
        out[i] = v;
    }
}

// ---------------------------------------------------------------------------
// tf32 mma.sync GEMM core (BM=128 BN=128 BK=16, 256 thr, 3-stage cp.async).
// B (weights) pre-rounded -> plain LDS for B-frags; A cvt'ed in-loop.
// ---------------------------------------------------------------------------
#define GKDIM 1024
#define GNDIM 1024
#define NKT 64
#define A_STRIDE 20
#define B_STRIDE 136
#define A_BYTES (128 * A_STRIDE * 4)
#define B_BYTES (16 * B_STRIDE * 4)
#define STAGE_BYTES (A_BYTES + B_BYTES)
#define GSTAGES 3
#define GEMM_SMEM (GSTAGES * STAGE_BYTES)

__device__ __forceinline__ void gemm_core(const float* __restrict__ A,
                                          const float* __restrict__ B,
                                          const float* __restrict__ bias,
                                          float* __restrict__ C,
                                          int m0, int n0, int useBias,
                                          char* dsmem)
{
    const int tid = threadIdx.x;
    const int wid = tid >> 5;
    const int lane = tid & 31;
    const int wm0 = (wid & 3) * 32;
    const int wn0 = (wid >> 2) * 64;
    const int qr = lane >> 2;
    const int qc = lane & 3;

    const uint32_t sbase = smem_to_u32(dsmem);

    float acc[2][8][4];
#pragma unroll
    for (int i = 0; i < 2; i++)
#pragma unroll
        for (int j = 0; j < 8; j++)
#pragma unroll
            for (int l = 0; l < 4; l++) acc[i][j][l] = 0.f;

    auto issue_stage = [&](int stage, int k0) {
        uint32_t aB = sbase + stage * STAGE_BYTES;
        uint32_t bB = aB + A_BYTES;
#pragma unroll
        for (int i = 0; i < 2; i++) {
            int idx = tid * 2 + i;
            int row = idx >> 2;
            int c4 = idx & 3;
            cp_async16(aB + row * (A_STRIDE * 4) + c4 * 16,
                       A + (size_t)(m0 + row) * GKDIM + k0 + c4 * 4);
            int krow = idx >> 5;
            int col = idx & 31;
            cp_async16(bB + krow * (B_STRIDE * 4) + col * 16,
                       B + (size_t)(k0 + krow) * GNDIM + n0 + col * 4);
        }
    };

    issue_stage(0, 0);
    CP_COMMIT();
    issue_stage(1, 16);
    CP_COMMIT();

    for (int kt = 0; kt < NKT; kt++) {
        int lt = kt + 2;
        if (lt < NKT) issue_stage(lt % GSTAGES, lt * 16);
        CP_COMMIT();
        CP_WAIT2();
        __syncthreads();

        const float* As = (const float*)(dsmem + (kt % GSTAGES) * STAGE_BYTES);
        const uint32_t* Bs = (const uint32_t*)(dsmem + (kt % GSTAGES) * STAGE_BYTES + A_BYTES);

#pragma unroll
        for (int ks = 0; ks < 2; ks++) {
            const int kb = ks * 8;
            uint32_t afr[2][4];
            uint32_t bfr[8][2];
#pragma unroll
            for (int mt = 0; mt < 2; mt++) {
                int mbase = wm0 + mt * 16;
                afr[mt][0] = f2tf32(As[(mbase + qr) * A_STRIDE + kb + qc]);
                afr[mt][1] = f2tf32(As[(mbase + qr + 8) * A_STRIDE + kb + qc]);
                afr[mt][2] = f2tf32(As[(mbase + qr) * A_STRIDE + kb + qc + 4]);
                afr[mt][3] = f2tf32(As[(mbase + qr + 8) * A_STRIDE + kb + qc + 4]);
            }
#pragma unroll
            for (int nt = 0; nt < 8; nt++) {
                int nc = wn0 + nt * 8 + qr;
                bfr[nt][0] = Bs[(kb + qc) * B_STRIDE + nc];        // pre-rounded
                bfr[nt][1] = Bs[(kb + qc + 4) * B_STRIDE + nc];
            }
#pragma unroll
            for (int mt = 0; mt < 2; mt++)
#pragma unroll
                for (int nt = 0; nt < 8; nt++)
                    mma_tf32(acc[mt][nt], afr[mt], bfr[nt]);
        }
        __syncthreads();
    }

#pragma unroll
    for (int mt = 0; mt < 2; mt++) {
        int r0 = m0 + wm0 + mt * 16 + qr;
#pragma unroll
        for (int nt = 0; nt < 8; nt++) {
            int col = n0 + wn0 + nt * 8 + 2 * qc;
            float bx = 0.f, by = 0.f;
            if (useBias) {
                float2 bb = *(const float2*)(bias + col);
                bx = bb.x; by = bb.y;
            }
            float2 v0 = {acc[mt][nt][0] + bx, acc[mt][nt][1] + by};
            float2 v1 = {acc[mt][nt][2] + bx, acc[mt][nt][3] + by};
            *(float2*)(C + (size_t)r0 * GNDIM + col) = v0;
            *(float2*)(C + (size_t)(r0 + 8) * GNDIM + col) = v1;
        }
    }
}

// Fused QKV: grid.x = 24 (3 weights x 8 N-tiles), grid.y = 64 (M-tiles)
__global__ __launch_bounds__(256)
void gemm_qkv_kernel(const float* __restrict__ x,
                     const float* __restrict__ Wq, const float* __restrict__ Wk,
                     const float* __restrict__ Wv,
                     float* __restrict__ q, float* __restrict__ k,
                     float* __restrict__ v)
{
    extern __shared__ char dsmem[];
    const int sel = blockIdx.x >> 3;
    const int n0 = (blockIdx.x & 7) * 128;
    const int m0 = blockIdx.y * 128;
    const float* B = (sel == 0) ? Wq : (sel == 1) ? Wk : Wv;
    float* C = (sel == 0) ? q : (sel == 1) ? k : v;
    gemm_core(x, B, nullptr, C, m0, n0, 0, dsmem);
}

__global__ __launch_bounds__(256)
void gemm_tc_kernel(const float* __restrict__ A, const float* __restrict__ B,
                    const float* __restrict__ bias, float* __restrict__ C,
                    int useBias)
{
    extern __shared__ char dsmem[];
    gemm_core(A, B, bias, C, blockIdx.y * 128, blockIdx.x * 128, useBias, dsmem);
}

// ---------------------------------------------------------------------------
// Flash attention (causal) with tf32 mma.sync — EXACT R6 version.
// Br=128, Bc=64, 256 threads (8 warps). Single-buffered K/V (2 CTA/SM).
// ---------------------------------------------------------------------------
struct AttnSmem {
    float Qs[128][68];
    float Ks[64][68];
    float Vs[64][72];
    float Ps[128][68];
    float red_max[2][128];
    float red_sum[2][128];
    float row_scale[128];
    float row_inv[128];
};   // ~106 KB

__global__ __launch_bounds__(256, 2)
void attn_mma_kernel(const float* __restrict__ q, const float* __restrict__ k,
                     const float* __restrict__ v, float* __restrict__ out)
{
    extern __shared__ char smem_raw[];
    AttnSmem& sm = *reinterpret_cast<AttnSmem*>(smem_raw);

    const int tid = threadIdx.x;
    const int wid = tid >> 5;
    const int lane = tid & 31;
    const int qr = lane >> 2;
    const int qc = lane & 3;
    const int q0 = (gridDim.x - 1 - blockIdx.x) * 128;   // heavy tiles first
    const int bh = blockIdx.y;
    const int b = bh >> 4;
    const int h = bh & 15;

    const size_t base = (size_t)b * SEQ * DMODEL + (size_t)h * HDIM;

    for (int idx = tid; idx < 2048; idx += 256) {
        int r = idx >> 4;
        int d4 = (idx & 15) << 2;
        float4 val = *(const float4*)(q + base + (size_t)(q0 + r) * DMODEL + d4);
        sm.Qs[r][d4 + 0] = val.x * 0.125f;
        sm.Qs[r][d4 + 1] = val.y * 0.125f;
        sm.Qs[r][d4 + 2] = val.z * 0.125f;
        sm.Qs[r][d4 + 3] = val.w * 0.125f;
    }

    auto load_k = [&](int k0) {
#pragma unroll
        for (int i = 0; i < 4; i++) {
            int idx = tid + i * 256;
            int c = idx >> 4;
            int d4 = (idx & 15) << 2;
            cp_async16(smem_to_u32(&sm.Ks[c][d4]),
                       k + base + (size_t)(k0 + c) * DMODEL + d4);
        }
    };
    auto load_v = [&](int k0) {
#pragma unroll
        for (int i = 0; i < 4; i++) {
            int idx = tid + i * 256;
            int c = idx >> 4;
            int d4 = (idx & 15) << 2;
            cp_async16(smem_to_u32(&sm.Vs[c][d4]),
                       v + base + (size_t)(k0 + c) * DMODEL + d4);
        }
    };

    const int srow = tid >> 1;
    const int shalf = tid & 1;
    const int sc0 = shalf * 32;
    float m_i = -INFINITY;
    float l_i = 0.f;

    float oacc[8][4];
#pragma unroll
    for (int nt = 0; nt < 8; nt++)
#pragma unroll
        for (int l = 0; l < 4; l++) oacc[nt][l] = 0.f;

    const int wm = (wid & 3) * 32;
    const int wn = (wid >> 2) * 32;

    const int nkt = (q0 >> 6) + 2;

    load_k(0);
    CP_COMMIT();

    for (int kt = 0; kt < nkt; kt++) {
        const int k0 = kt * 64;

        load_v(k0);
        CP_COMMIT();
        CP_WAIT0();
        __syncthreads();

        // ---- S = Q @ K^T (warp tile 32x32) ----
        float sacc[2][4][4];
#pragma unroll
        for (int mt = 0; mt < 2; mt++)
#pragma unroll
            for (int nt = 0; nt < 4; nt++)
#pragma unroll
                for (int l = 0; l < 4; l++) sacc[mt][nt][l] = 0.f;

#pragma unroll
        for (int ks = 0; ks < 8; ks++) {
            const int kb = ks * 8;
            uint32_t afr[2][4];
            uint32_t bfr[4][2];
#pragma unroll
            for (int mt = 0; mt < 2; mt++) {
                int mbase = wm + mt * 16;
                afr[mt][0] = f2tf32(sm.Qs[mbase + qr][kb + qc]);
                afr[mt][1] = f2tf32(sm.Qs[mbase + qr + 8][kb + qc]);
                afr[mt][2] = f2tf32(sm.Qs[mbase + qr][kb + qc + 4]);
                afr[mt][3] = f2tf32(sm.Qs[mbase + qr + 8][kb + qc + 4]);
            }
#pragma unroll
            for (int nt = 0; nt < 4; nt++) {
                int nc = wn + nt * 8 + qr;
                bfr[nt][0] = f2tf32(sm.Ks[nc][kb + qc]);
                bfr[nt][1] = f2tf32(sm.Ks[nc][kb + qc + 4]);
            }
#pragma unroll
            for (int mt = 0; mt < 2; mt++)
#pragma unroll
                for (int nt = 0; nt < 4; nt++)
                    mma_tf32(sacc[mt][nt], afr[mt], bfr[nt]);
        }

        // Write S fragments to Ps
#pragma unroll
        for (int mt = 0; mt < 2; mt++) {
            int r0 = wm + mt * 16 + qr;
#pragma unroll
            for (int nt = 0; nt < 4; nt++) {
                int col = wn + nt * 8 + 2 * qc;
                *(float2*)&sm.Ps[r0][col]     = make_float2(sacc[mt][nt][0], sacc[mt][nt][1]);
                *(float2*)&sm.Ps[r0 + 8][col] = make_float2(sacc[mt][nt][2], sacc[mt][nt][3]);
            }
        }
        __syncthreads();

        // Prefetch K(kt+1) — overlaps softmax + PV
        if (kt + 1 < nkt) {
            load_k(k0 + 64);
            CP_COMMIT();
        }

        // ---- Online softmax ----
        {
            const int climit = q0 + srow - k0;
            const bool nomask = (climit >= sc0 + 31);
            float mloc = -INFINITY;
            if (nomask) {
#pragma unroll
                for (int c4 = 0; c4 < 8; c4++) {
                    float4 vv = *(const float4*)&sm.Ps[srow][sc0 + c4 * 4];
                    mloc = fmaxf(mloc, fmaxf(fmaxf(vv.x, vv.y), fmaxf(vv.z, vv.w)));
                }
            } else {
#pragma unroll
                for (int c4 = 0; c4 < 8; c4++) {
                    float4 vv = *(const float4*)&sm.Ps[srow][sc0 + c4 * 4];
                    int c = sc0 + c4 * 4;
                    if (c + 0 <= climit) mloc = fmaxf(mloc, vv.x);
                    if (c + 1 <= climit) mloc = fmaxf(mloc, vv.y);
                    if (c + 2 <= climit) mloc = fmaxf(mloc, vv.z);
                    if (c + 3 <= climit) mloc = fmaxf(mloc, vv.w);
                }
            }
            sm.red_max[shalf][srow] = mloc;
            __syncthreads();
            float mtile = fmaxf(sm.red_max[0][srow], sm.red_max[1][srow]);
            float mnew = fmaxf(m_i, mtile);
            float rs = __expf(m_i - mnew);
            if (shalf == 0) sm.row_scale[srow] = rs;

            float lsum = 0.f;
            if (nomask) {
#pragma unroll
                for (int c4 = 0; c4 < 8; c4++) {
                    float4 vv = *(float4*)&sm.Ps[srow][sc0 + c4 * 4];
                    vv.x = __expf(vv.x - mnew);
                    vv.y = __expf(vv.y - mnew);
                    vv.z = __expf(vv.z - mnew);
                    vv.w = __expf(vv.w - mnew);
                    lsum += vv.x + vv.y + vv.z + vv.w;
                    *(float4*)&sm.Ps[srow][sc0 + c4 * 4] = vv;
                }
            } else {
#pragma unroll
                for (int c4 = 0; c4 < 8; c4++) {
                    float4 vv = *(float4*)&sm.Ps[srow][sc0 + c4 * 4];
                    int c = sc0 + c4 * 4;
                    vv.x = (c + 0 <= climit) ? __expf(vv.x - mnew) : 0.f;
                    vv.y = (c + 1 <= climit) ? __expf(vv.y - mnew) : 0.f;
                    vv.z = (c + 2 <= climit) ? __expf(vv.z - mnew) : 0.f;
                    vv.w = (c + 3 <= climit) ? __expf(vv.w - mnew) : 0.f;
                    lsum += vv.x + vv.y + vv.z + vv.w;
                    *(float4*)&sm.Ps[srow][sc0 + c4 * 4] = vv;
                }
            }
            sm.red_sum[shalf][srow] = lsum;
            __syncthreads();
            l_i = l_i * rs + sm.red_sum[0][srow] + sm.red_sum[1][srow];
            m_i = mnew;
        }

        // ---- O = O*rs + P @ V (warp tile 16x64) ----
        {
            const int mbase = wid * 16;
            float rs0 = sm.row_scale[mbase + qr];
            float rs1 = sm.row_scale[mbase + qr + 8];
#pragma unroll
            for (int nt = 0; nt < 8; nt++) {
                oacc[nt][0] *= rs0; oacc[nt][1] *= rs0;
                oacc[nt][2] *= rs1; oacc[nt][3] *= rs1;
            }
#pragma unroll
            for (int ks = 0; ks < 8; ks++) {
                const int kb = ks * 8;
                uint32_t afr[4];
                afr[0] = f2tf32(sm.Ps[mbase + qr][kb + qc]);
                afr[1] = f2tf32(sm.Ps[mbase + qr + 8][kb + qc]);
                afr[2] = f2tf32(sm.Ps[mbase + qr][kb + qc + 4]);
                afr[3] = f2tf32(sm.Ps[mbase + qr + 8][kb + qc + 4]);
                uint32_t bfr[8][2];
#pragma unroll
                for (int nt = 0; nt < 8; nt++) {
                    int nc = nt * 8 + qr;
                    bfr[nt][0] = f2tf32(sm.Vs[kb + qc][nc]);
                    bfr[nt][1] = f2tf32(sm.Vs[kb + qc + 4][nc]);
                }
#pragma unroll
                for (int nt = 0; nt < 8; nt++)
                    mma_tf32(oacc[nt], afr, bfr[nt]);
            }
        }
        __syncthreads();
    }

    // Final normalization
    if (shalf == 0) sm.row_inv[srow] = 1.f / l_i;
    __syncthreads();

    {
        const int mbase = wid * 16;
        float inv0 = sm.row_inv[mbase + qr];
        float inv1 = sm.row_inv[mbase + qr + 8];
        size_t r0 = base + (size_t)(q0 + mbase + qr) * DMODEL;
        size_t r1 = base + (size_t)(q0 + mbase + qr + 8) * DMODEL;
#pragma unroll
        for (int nt = 0; nt < 8; nt++) {
            int col = nt * 8 + 2 * qc;
            *(float2*)(out + r0 + col) = make_float2(oacc[nt][0] * inv0, oacc[nt][1] * inv0);
            *(float2*)(out + r1 + col) = make_float2(oacc[nt][2] * inv1, oacc[nt][3] * inv1);
        }
    }
}

// ---------------------------------------------------------------------------
// Launch
// ---------------------------------------------------------------------------
extern "C" void kernel_launch(void* const* d_in, const int* in_sizes, int n_in,
                              void* d_out, int out_size)
{
    const float* x  = (const float*)d_in[0];
    const float* Wq = (const float*)d_in[1];
    const float* Wk = (const float*)d_in[2];
    const float* Wv = (const float*)d_in[3];
    const float* Wo = (const float*)d_in[4];
    const float* bo = (const float*)d_in[5];
    float* out = (float*)d_out;

    float *qp, *kp, *vp, *ap, *wr;
    cudaGetSymbolAddress((void**)&qp, g_q);
    cudaGetSymbolAddress((void**)&kp, g_k);
    cudaGetSymbolAddress((void**)&vp, g_v);
    cudaGetSymbolAddress((void**)&ap, g_attn);
    cudaGetSymbolAddress((void**)&wr, g_wr);
    float* wrq = wr;
    float* wrk = wr + 1 * DMODEL * DMODEL;
    float* wrv = wr + 2 * DMODEL * DMODEL;
    float* wro = wr + 3 * DMODEL * DMODEL;

    cudaFuncSetAttribute(gemm_qkv_kernel, cudaFuncAttributeMaxDynamicSharedMemorySize, GEMM_SMEM);
    cudaFuncSetAttribute(gemm_tc_kernel, cudaFuncAttributeMaxDynamicSharedMemorySize, GEMM_SMEM);
    cudaFuncSetAttribute(attn_mma_kernel, cudaFuncAttributeMaxDynamicSharedMemorySize,
                         (int)sizeof(AttnSmem));

    // Pre-round weights to tf32 bit patterns (bit-identical to in-loop cvt)
    const int WN4 = DMODEL * DMODEL / 4;
    round_tf32_kernel<<<(WN4 + 255) / 256, 256>>>((const float4*)Wq, (float4*)wrq, WN4);
    round_tf32_kernel<<<(WN4 + 255) / 256, 256>>>((const float4*)Wk, (float4*)wrk, WN4);
    round_tf32_kernel<<<(WN4 + 255) / 256, 256>>>((const float4*)Wv, (float4*)wrv, WN4);
    round_tf32_kernel<<<(WN4 + 255) / 256, 256>>>((const float4*)Wo, (float4*)wro, WN4);

    // Fused QKV projections
    dim3 qkvgrid(24, MTOT / 128);
    gemm_qkv_kernel<<<qkvgrid, 256, GEMM_SMEM>>>(x, wrq, wrk, wrv, qp, kp, vp);

    // Causal flash attention
    dim3 agrid(SEQ / 128, BATCH * NHEADS);
    attn_mma_kernel<<<agrid, 256, sizeof(AttnSmem)>>>(qp, kp, vp, ap);

    // Output projection + bias
    dim3 ggrid(GNDIM / 128, MTOT / 128);
    gemm_tc_kernel<<<ggrid, 256, GEMM_SMEM>>>(ap, wro, bo, out, 1);
}

// round 10
// speedup vs baseline: 1.4902x; 1.0130x over previous
#include <cuda_runtime.h>
#include <cuda_bf16.h>
#include <math.h>
#include <stdint.h>

// Problem constants
#define BATCH 4
#define SEQ 2048
#define DMODEL 1024
#define NHEADS 16
#define HDIM 64
#define MTOT (BATCH * SEQ)          // 8192 rows

// ---------------------------------------------------------------------------
// Scratch (device globals: allocation-free, graph-safe)
// ---------------------------------------------------------------------------
__device__ float g_q[MTOT * DMODEL];
__device__ float g_k[MTOT * DMODEL];
__device__ float g_v[MTOT * DMODEL];
__device__ float g_attn[MTOT * DMODEL];
__device__ float g_xr[MTOT * DMODEL];        // tf32-rounded x
__device__ float g_wr[4][DMODEL * DMODEL];   // tf32-rounded Wq,Wk,Wv,Wo

// ---------------------------------------------------------------------------
// Helpers
// ---------------------------------------------------------------------------
__device__ __forceinline__ uint32_t smem_to_u32(const void* p) {
    uint32_t a;
    asm("{ .reg .u64 t; cvta.to.shared.u64 t, %1; cvt.u32.u64 %0, t; }"
        : "=r"(a) : "l"(p));
    return a;
}
__device__ __forceinline__ void cp_async16(uint32_t dst, const void* src) {
    asm volatile("cp.async.cg.shared.global [%0], [%1], 16;" :: "r"(dst), "l"(src));
}
#define CP_COMMIT() asm volatile("cp.async.commit_group;" ::: "memory")
#define CP_WAIT0()  asm volatile("cp.async.wait_group 0;" ::: "memory")
#define CP_WAIT2()  asm volatile("cp.async.wait_group 2;" ::: "memory")

__device__ __forceinline__ uint32_t f2tf32(float f) {
    uint32_t r;
    asm("cvt.rna.tf32.f32 %0, %1;" : "=r"(r) : "f"(f));
    return r;
}
__device__ __forceinline__ float roundtf(float f) {
    return __uint_as_float(f2tf32(f));
}
__device__ __forceinline__ void mma_tf32(float* c, const uint32_t* a, const uint32_t* b) {
    asm volatile(
        "mma.sync.aligned.m16n8k8.row.col.f32.tf32.tf32.f32 "
        "{%0,%1,%2,%3}, {%4,%5,%6,%7}, {%8,%9}, {%0,%1,%2,%3};"
        : "+f"(c[0]), "+f"(c[1]), "+f"(c[2]), "+f"(c[3])
        : "r"(a[0]), "r"(a[1]), "r"(a[2]), "r"(a[3]), "r"(b[0]), "r"(b[1]));
}

// ---------------------------------------------------------------------------
// Pre-pass: round fp32 -> tf32 bit pattern. Grid-strided, 4 float4/thread.
// ---------------------------------------------------------------------------
__global__ __launch_bounds__(256)
void round_x_kernel(const float4* __restrict__ in, float4* __restrict__ out, int n4)
{
    int stride = gridDim.x * 256;
    for (int i = blockIdx.x * 256 + threadIdx.x; i < n4; i += stride) {
        float4 v = in[i];
        v.x = roundtf(v.x);
        v.y = roundtf(v.y);
        v.z = roundtf(v.z);
        v.w = roundtf(v.w);
        out[i] = v;
    }
}

// All four weights in one launch; blockIdx.y selects matrix.
__global__ __launch_bounds__(256)
void round_w_kernel(const float4* __restrict__ w0, const float4* __restrict__ w1,
                    const float4* __restrict__ w2, const float4* __restrict__ w3,
                    float4* __restrict__ out, int n4)
{
    const float4* in = (blockIdx.y == 0) ? w0 : (blockIdx.y == 1) ? w1
                     : (blockIdx.y == 2) ? w2 : w3;
    float4* dst = out + (size_t)blockIdx.y * n4;
    int stride = gridDim.x * 256;
    for (int i = blockIdx.x * 256 + threadIdx.x; i < n4; i += stride) {
        float4 v = in[i];
        v.x = roundtf(v.x);
        v.y = roundtf(v.y);
        v.z = roundtf(v.z);
        v.w = roundtf(v.w);
        dst[i] = v;
    }
}

// ---------------------------------------------------------------------------
// tf32 mma.sync GEMM core (BM=128 BN=128 BK=16, 256 thr, 3-stage cp.async).
// A_PRE: A is pre-rounded (plain LDS); else cvt in-loop. B always pre-rounded.
// ---------------------------------------------------------------------------
#define GKDIM 1024
#define GNDIM 1024
#define NKT 64
#define A_STRIDE 20
#define B_STRIDE 136
#define A_BYTES (128 * A_STRIDE * 4)
#define B_BYTES (16 * B_STRIDE * 4)
#define STAGE_BYTES (A_BYTES + B_BYTES)
#define GSTAGES 3
#define GEMM_SMEM (GSTAGES * STAGE_BYTES)

template <bool A_PRE>
__device__ __forceinline__ void gemm_core(const float* __restrict__ A,
                                          const float* __restrict__ B,
                                          const float* __restrict__ bias,
                                          float* __restrict__ C,
                                          int m0, int n0, int useBias,
                                          char* dsmem)
{
    const int tid = threadIdx.x;
    const int wid = tid >> 5;
    const int lane = tid & 31;
    const int wm0 = (wid & 3) * 32;
    const int wn0 = (wid >> 2) * 64;
    const int qr = lane >> 2;
    const int qc = lane & 3;

    const uint32_t sbase = smem_to_u32(dsmem);

    float acc[2][8][4];
#pragma unroll
    for (int i = 0; i < 2; i++)
#pragma unroll
        for (int j = 0; j < 8; j++)
#pragma unroll
            for (int l = 0; l < 4; l++) acc[i][j][l] = 0.f;

    auto issue_stage = [&](int stage, int k0) {
        uint32_t aB = sbase + stage * STAGE_BYTES;
        uint32_t bB = aB + A_BYTES;
#pragma unroll
        for (int i = 0; i < 2; i++) {
            int idx = tid * 2 + i;
            int row = idx >> 2;
            int c4 = idx & 3;
            cp_async16(aB + row * (A_STRIDE * 4) + c4 * 16,
                       A + (size_t)(m0 + row) * GKDIM + k0 + c4 * 4);
            int krow = idx >> 5;
            int col = idx & 31;
            cp_async16(bB + krow * (B_STRIDE * 4) + col * 16,
                       B + (size_t)(k0 + krow) * GNDIM + n0 + col * 4);
        }
    };

    issue_stage(0, 0);
    CP_COMMIT();
    issue_stage(1, 16);
    CP_COMMIT();

    for (int kt = 0; kt < NKT; kt++) {
        int lt = kt + 2;
        if (lt < NKT) issue_stage(lt % GSTAGES, lt * 16);
        CP_COMMIT();
        CP_WAIT2();
        __syncthreads();

        const float* As = (const float*)(dsmem + (kt % GSTAGES) * STAGE_BYTES);
        const uint32_t* Asu = (const uint32_t*)As;
        const uint32_t* Bs = (const uint32_t*)(dsmem + (kt % GSTAGES) * STAGE_BYTES + A_BYTES);

#pragma unroll
        for (int ks = 0; ks < 2; ks++) {
            const int kb = ks * 8;
            uint32_t afr[2][4];
            uint32_t bfr[8][2];
#pragma unroll
            for (int mt = 0; mt < 2; mt++) {
                int mbase = wm0 + mt * 16;
                if (A_PRE) {
                    afr[mt][0] = Asu[(mbase + qr) * A_STRIDE + kb + qc];
                    afr[mt][1] = Asu[(mbase + qr + 8) * A_STRIDE + kb + qc];
                    afr[mt][2] = Asu[(mbase + qr) * A_STRIDE + kb + qc + 4];
                    afr[mt][3] = Asu[(mbase + qr + 8) * A_STRIDE + kb + qc + 4];
                } else {
                    afr[mt][0] = f2tf32(As[(mbase + qr) * A_STRIDE + kb + qc]);
                    afr[mt][1] = f2tf32(As[(mbase + qr + 8) * A_STRIDE + kb + qc]);
                    afr[mt][2] = f2tf32(As[(mbase + qr) * A_STRIDE + kb + qc + 4]);
                    afr[mt][3] = f2tf32(As[(mbase + qr + 8) * A_STRIDE + kb + qc + 4]);
                }
            }
#pragma unroll
            for (int nt = 0; nt < 8; nt++) {
                int nc = wn0 + nt * 8 + qr;
                bfr[nt][0] = Bs[(kb + qc) * B_STRIDE + nc];        // pre-rounded
                bfr[nt][1] = Bs[(kb + qc + 4) * B_STRIDE + nc];
            }
#pragma unroll
            for (int mt = 0; mt < 2; mt++)
#pragma unroll
                for (int nt = 0; nt < 8; nt++)
                    mma_tf32(acc[mt][nt], afr[mt], bfr[nt]);
        }
        __syncthreads();
    }

#pragma unroll
    for (int mt = 0; mt < 2; mt++) {
        int r0 = m0 + wm0 + mt * 16 + qr;
#pragma unroll
        for (int nt = 0; nt < 8; nt++) {
            int col = n0 + wn0 + nt * 8 + 2 * qc;
            float bx = 0.f, by = 0.f;
            if (useBias) {
                float2 bb = *(const float2*)(bias + col);
                bx = bb.x; by = bb.y;
            }
            float2 v0 = {acc[mt][nt][0] + bx, acc[mt][nt][1] + by};
            float2 v1 = {acc[mt][nt][2] + bx, acc[mt][nt][3] + by};
            *(float2*)(C + (size_t)r0 * GNDIM + col) = v0;
            *(float2*)(C + (size_t)(r0 + 8) * GNDIM + col) = v1;
        }
    }
}

// Fused QKV: grid.x = 24 (3 weights x 8 N-tiles), grid.y = 64 (M-tiles)
__global__ __launch_bounds__(256)
void gemm_qkv_kernel(const float* __restrict__ x,
                     const float* __restrict__ Wq, const float* __restrict__ Wk,
                     const float* __restrict__ Wv,
                     float* __restrict__ q, float* __restrict__ k,
                     float* __restrict__ v)
{
    extern __shared__ char dsmem[];
    const int sel = blockIdx.x >> 3;
    const int n0 = (blockIdx.x & 7) * 128;
    const int m0 = blockIdx.y * 128;
    const float* B = (sel == 0) ? Wq : (sel == 1) ? Wk : Wv;
    float* C = (sel == 0) ? q : (sel == 1) ? k : v;
    gemm_core<true>(x, B, nullptr, C, m0, n0, 0, dsmem);
}

__global__ __launch_bounds__(256)
void gemm_tc_kernel(const float* __restrict__ A, const float* __restrict__ B,
                    const float* __restrict__ bias, float* __restrict__ C,
                    int useBias)
{
    extern __shared__ char dsmem[];
    gemm_core<false>(A, B, bias, C, blockIdx.y * 128, blockIdx.x * 128, useBias, dsmem);
}

// ---------------------------------------------------------------------------
// Flash attention (causal) with tf32 mma.sync — EXACT R6/R8 version.
// Br=128, Bc=64, 256 threads (8 warps). Single-buffered K/V (2 CTA/SM).
// ---------------------------------------------------------------------------
struct AttnSmem {
    float Qs[128][68];
    float Ks[64][68];
    float Vs[64][72];
    float Ps[128][68];
    float red_max[2][128];
    float red_sum[2][128];
    float row_scale[128];
    float row_inv[128];
};   // ~106 KB

__global__ __launch_bounds__(256, 2)
void attn_mma_kernel(const float* __restrict__ q, const float* __restrict__ k,
                     const float* __restrict__ v, float* __restrict__ out)
{
    extern __shared__ char smem_raw[];
    AttnSmem& sm = *reinterpret_cast<AttnSmem*>(smem_raw);

    const int tid = threadIdx.x;
    const int wid = tid >> 5;
    const int lane = tid & 31;
    const int qr = lane >> 2;
    const int qc = lane & 3;
    const int q0 = (gridDim.x - 1 - blockIdx.x) * 128;   // heavy tiles first
    const int bh = blockIdx.y;
    const int b = bh >> 4;
    const int h = bh & 15;

    const size_t base = (size_t)b * SEQ * DMODEL + (size_t)h * HDIM;

    for (int idx = tid; idx < 2048; idx += 256) {
        int r = idx >> 4;
        int d4 = (idx & 15) << 2;
        float4 val = *(const float4*)(q + base + (size_t)(q0 + r) * DMODEL + d4);
        sm.Qs[r][d4 + 0] = val.x * 0.125f;
        sm.Qs[r][d4 + 1] = val.y * 0.125f;
        sm.Qs[r][d4 + 2] = val.z * 0.125f;
        sm.Qs[r][d4 + 3] = val.w * 0.125f;
    }

    auto load_k = [&](int k0) {
#pragma unroll
        for (int i = 0; i < 4; i++) {
            int idx = tid + i * 256;
            int c = idx >> 4;
            int d4 = (idx & 15) << 2;
            cp_async16(smem_to_u32(&sm.Ks[c][d4]),
                       k + base + (size_t)(k0 + c) * DMODEL + d4);
        }
    };
    auto load_v = [&](int k0) {
#pragma unroll
        for (int i = 0; i < 4; i++) {
            int idx = tid + i * 256;
            int c = idx >> 4;
            int d4 = (idx & 15) << 2;
            cp_async16(smem_to_u32(&sm.Vs[c][d4]),
                       v + base + (size_t)(k0 + c) * DMODEL + d4);
        }
    };

    const int srow = tid >> 1;
    const int shalf = tid & 1;
    const int sc0 = shalf * 32;
    float m_i = -INFINITY;
    float l_i = 0.f;

    float oacc[8][4];
#pragma unroll
    for (int nt = 0; nt < 8; nt++)
#pragma unroll
        for (int l = 0; l < 4; l++) oacc[nt][l] = 0.f;

    const int wm = (wid & 3) * 32;
    const int wn = (wid >> 2) * 32;

    const int nkt = (q0 >> 6) + 2;

    load_k(0);
    CP_COMMIT();

    for (int kt = 0; kt < nkt; kt++) {
        const int k0 = kt * 64;

        load_v(k0);
        CP_COMMIT();
        CP_WAIT0();
        __syncthreads();

        // ---- S = Q @ K^T (warp tile 32x32) ----
        float sacc[2][4][4];
#pragma unroll
        for (int mt = 0; mt < 2; mt++)
#pragma unroll
            for (int nt = 0; nt < 4; nt++)
#pragma unroll
                for (int l = 0; l < 4; l++) sacc[mt][nt][l] = 0.f;

#pragma unroll
        for (int ks = 0; ks < 8; ks++) {
            const int kb = ks * 8;
            uint32_t afr[2][4];
            uint32_t bfr[4][2];
#pragma unroll
            for (int mt = 0; mt < 2; mt++) {
                int mbase = wm + mt * 16;
                afr[mt][0] = f2tf32(sm.Qs[mbase + qr][kb + qc]);
                afr[mt][1] = f2tf32(sm.Qs[mbase + qr + 8][kb + qc]);
                afr[mt][2] = f2tf32(sm.Qs[mbase + qr][kb + qc + 4]);
                afr[mt][3] = f2tf32(sm.Qs[mbase + qr + 8][kb + qc + 4]);
            }
#pragma unroll
            for (int nt = 0; nt < 4; nt++) {
                int nc = wn + nt * 8 + qr;
                bfr[nt][0] = f2tf32(sm.Ks[nc][kb + qc]);
                bfr[nt][1] = f2tf32(sm.Ks[nc][kb + qc + 4]);
            }
#pragma unroll
            for (int mt = 0; mt < 2; mt++)
#pragma unroll
                for (int nt = 0; nt < 4; nt++)
                    mma_tf32(sacc[mt][nt], afr[mt], bfr[nt]);
        }

        // Write S fragments to Ps
#pragma unroll
        for (int mt = 0; mt < 2; mt++) {
            int r0 = wm + mt * 16 + qr;
#pragma unroll
            for (int nt = 0; nt < 4; nt++) {
                int col = wn + nt * 8 + 2 * qc;
                *(float2*)&sm.Ps[r0][col]     = make_float2(sacc[mt][nt][0], sacc[mt][nt][1]);
                *(float2*)&sm.Ps[r0 + 8][col] = make_float2(sacc[mt][nt][2], sacc[mt][nt][3]);
            }
        }
        __syncthreads();

        // Prefetch K(kt+1) — overlaps softmax + PV
        if (kt + 1 < nkt) {
            load_k(k0 + 64);
            CP_COMMIT();
        }

        // ---- Online softmax ----
        {
            const int climit = q0 + srow - k0;
            const bool nomask = (climit >= sc0 + 31);
            float mloc = -INFINITY;
            if (nomask) {
#pragma unroll
                for (int c4 = 0; c4 < 8; c4++) {
                    float4 vv = *(const float4*)&sm.Ps[srow][sc0 + c4 * 4];
                    mloc = fmaxf(mloc, fmaxf(fmaxf(vv.x, vv.y), fmaxf(vv.z, vv.w)));
                }
            } else {
#pragma unroll
                for (int c4 = 0; c4 < 8; c4++) {
                    float4 vv = *(const float4*)&sm.Ps[srow][sc0 + c4 * 4];
                    int c = sc0 + c4 * 4;
                    if (c + 0 <= climit) mloc = fmaxf(mloc, vv.x);
                    if (c + 1 <= climit) mloc = fmaxf(mloc, vv.y);
                    if (c + 2 <= climit) mloc = fmaxf(mloc, vv.z);
                    if (c + 3 <= climit) mloc = fmaxf(mloc, vv.w);
                }
            }
            sm.red_max[shalf][srow] = mloc;
            __syncthreads();
            float mtile = fmaxf(sm.red_max[0][srow], sm.red_max[1][srow]);
            float mnew = fmaxf(m_i, mtile);
            float rs = __expf(m_i - mnew);
            if (shalf == 0) sm.row_scale[srow] = rs;

            float lsum = 0.f;
            if (nomask) {
#pragma unroll
                for (int c4 = 0; c4 < 8; c4++) {
                    float4 vv = *(float4*)&sm.Ps[srow][sc0 + c4 * 4];
                    vv.x = __expf(vv.x - mnew);
                    vv.y = __expf(vv.y - mnew);
                    vv.z = __expf(vv.z - mnew);
                    vv.w = __expf(vv.w - mnew);
                    lsum += vv.x + vv.y + vv.z + vv.w;
                    *(float4*)&sm.Ps[srow][sc0 + c4 * 4] = vv;
                }
            } else {
#pragma unroll
                for (int c4 = 0; c4 < 8; c4++) {
                    float4 vv = *(float4*)&sm.Ps[srow][sc0 + c4 * 4];
                    int c = sc0 + c4 * 4;
                    vv.x = (c + 0 <= climit) ? __expf(vv.x - mnew) : 0.f;
                    vv.y = (c + 1 <= climit) ? __expf(vv.y - mnew) : 0.f;
                    vv.z = (c + 2 <= climit) ? __expf(vv.z - mnew) : 0.f;
                    vv.w = (c + 3 <= climit) ? __expf(vv.w - mnew) : 0.f;
                    lsum += vv.x + vv.y + vv.z + vv.w;
                    *(float4*)&sm.Ps[srow][sc0 + c4 * 4] = vv;
                }
            }
            sm.red_sum[shalf][srow] = lsum;
            __syncthreads();
            l_i = l_i * rs + sm.red_sum[0][srow] + sm.red_sum[1][srow];
            m_i = mnew;
        }

        // ---- O = O*rs + P @ V (warp tile 16x64) ----
        {
            const int mbase = wid * 16;
            float rs0 = sm.row_scale[mbase + qr];
            float rs1 = sm.row_scale[mbase + qr + 8];
#pragma unroll
            for (int nt = 0; nt < 8; nt++) {
                oacc[nt][0] *= rs0; oacc[nt][1] *= rs0;
                oacc[nt][2] *= rs1; oacc[nt][3] *= rs1;
            }
#pragma unroll
            for (int ks = 0; ks < 8; ks++) {
                const int kb = ks * 8;
                uint32_t afr[4];
                afr[0] = f2tf32(sm.Ps[mbase + qr][kb + qc]);
                afr[1] = f2tf32(sm.Ps[mbase + qr + 8][kb + qc]);
                afr[2] = f2tf32(sm.Ps[mbase + qr][kb + qc + 4]);
                afr[3] = f2tf32(sm.Ps[mbase + qr + 8][kb + qc + 4]);
                uint32_t bfr[8][2];
#pragma unroll
                for (int nt = 0; nt < 8; nt++) {
                    int nc = nt * 8 + qr;
                    bfr[nt][0] = f2tf32(sm.Vs[kb + qc][nc]);
                    bfr[nt][1] = f2tf32(sm.Vs[kb + qc + 4][nc]);
                }
#pragma unroll
                for (int nt = 0; nt < 8; nt++)
                    mma_tf32(oacc[nt], afr, bfr[nt]);
            }
        }
        __syncthreads();
    }

    // Final normalization
    if (shalf == 0) sm.row_inv[srow] = 1.f / l_i;
    __syncthreads();

    {
        const int mbase = wid * 16;
        float inv0 = sm.row_inv[mbase + qr];
        float inv1 = sm.row_inv[mbase + qr + 8];
        size_t r0 = base + (size_t)(q0 + mbase + qr) * DMODEL;
        size_t r1 = base + (size_t)(q0 + mbase + qr + 8) * DMODEL;
#pragma unroll
        for (int nt = 0; nt < 8; nt++) {
            int col = nt * 8 + 2 * qc;
            *(float2*)(out + r0 + col) = make_float2(oacc[nt][0] * inv0, oacc[nt][1] * inv0);
            *(float2*)(out + r1 + col) = make_float2(oacc[nt][2] * inv1, oacc[nt][3] * inv1);
        }
    }
}

// ---------------------------------------------------------------------------
// Launch
// ---------------------------------------------------------------------------
extern "C" void kernel_launch(void* const* d_in, const int* in_sizes, int n_in,
                              void* d_out, int out_size)
{
    const float* x  = (const float*)d_in[0];
    const float* Wq = (const float*)d_in[1];
    const float* Wk = (const float*)d_in[2];
    const float* Wv = (const float*)d_in[3];
    const float* Wo = (const float*)d_in[4];
    const float* bo = (const float*)d_in[5];
    float* out = (float*)d_out;

    float *qp, *kp, *vp, *ap, *xr, *wr;
    cudaGetSymbolAddress((void**)&qp, g_q);
    cudaGetSymbolAddress((void**)&kp, g_k);
    cudaGetSymbolAddress((void**)&vp, g_v);
    cudaGetSymbolAddress((void**)&ap, g_attn);
    cudaGetSymbolAddress((void**)&xr, g_xr);
    cudaGetSymbolAddress((void**)&wr, g_wr);
    float* wrq = wr;
    float* wro = wr + 3 * DMODEL * DMODEL;

    cudaFuncSetAttribute(gemm_qkv_kernel, cudaFuncAttributeMaxDynamicSharedMemorySize, GEMM_SMEM);
    cudaFuncSetAttribute(gemm_tc_kernel, cudaFuncAttributeMaxDynamicSharedMemorySize, GEMM_SMEM);
    cudaFuncSetAttribute(attn_mma_kernel, cudaFuncAttributeMaxDynamicSharedMemorySize,
                         (int)sizeof(AttnSmem));

    // Pre-round x and weights (grid-strided, 4 float4/thread)
    const int XN4 = MTOT * DMODEL / 4;       // 2097152
    const int WN4 = DMODEL * DMODEL / 4;     // 262144
    round_x_kernel<<<XN4 / (256 * 4), 256>>>((const float4*)x, (float4*)xr, XN4);
    dim3 wgrid(WN4 / (256 * 4), 4);          // (256, 4)
    round_w_kernel<<<wgrid, 256>>>((const float4*)Wq, (const float4*)Wk,
                                   (const float4*)Wv, (const float4*)Wo,
                                   (float4*)wr, WN4);

    // Fused QKV projections (zero-cvt inner loop)
    dim3 qkvgrid(24, MTOT / 128);
    gemm_qkv_kernel<<<qkvgrid, 256, GEMM_SMEM>>>(xr, wrq, wrq + WN4 * 4, wrq + 2 * WN4 * 4,
                                                 qp, kp, vp);

    // Causal flash attention
    dim3 agrid(SEQ / 128, BATCH * NHEADS);
    attn_mma_kernel<<<agrid, 256, sizeof(AttnSmem)>>>(qp, kp, vp, ap);

    // Output projection + bias (A cvt in-loop)
    dim3 ggrid(GNDIM / 128, MTOT / 128);
    gemm_tc_kernel<<<ggrid, 256, GEMM_SMEM>>>(ap, wro, bo, out, 1);
}

// round 11
// speedup vs baseline: 1.5508x; 1.0407x over previous
#include <cuda_runtime.h>
#include <cuda_bf16.h>
#include <math.h>
#include <stdint.h>

// Problem constants
#define BATCH 4
#define SEQ 2048
#define DMODEL 1024
#define NHEADS 16
#define HDIM 64
#define MTOT (BATCH * SEQ)          // 8192 rows

// ---------------------------------------------------------------------------
// Scratch (device globals: allocation-free, graph-safe)
// ---------------------------------------------------------------------------
__device__ float g_q[MTOT * DMODEL];
__device__ float g_k[MTOT * DMODEL];
__device__ float g_v[MTOT * DMODEL];
__device__ float g_attn[MTOT * DMODEL];
__device__ float g_xr[MTOT * DMODEL];        // tf32-rounded x
__device__ float g_wr[4][DMODEL * DMODEL];   // tf32-rounded Wq,Wk,Wv,Wo

// ---------------------------------------------------------------------------
// Helpers
// ---------------------------------------------------------------------------
__device__ __forceinline__ uint32_t smem_to_u32(const void* p) {
    uint32_t a;
    asm("{ .reg .u64 t; cvta.to.shared.u64 t, %1; cvt.u32.u64 %0, t; }"
        : "=r"(a) : "l"(p));
    return a;
}
__device__ __forceinline__ void cp_async16(uint32_t dst, const void* src) {
    asm volatile("cp.async.cg.shared.global [%0], [%1], 16;" :: "r"(dst), "l"(src));
}
#define CP_COMMIT() asm volatile("cp.async.commit_group;" ::: "memory")
#define CP_WAIT0()  asm volatile("cp.async.wait_group 0;" ::: "memory")
#define CP_WAIT2()  asm volatile("cp.async.wait_group 2;" ::: "memory")

__device__ __forceinline__ uint32_t f2tf32(float f) {
    uint32_t r;
    asm("cvt.rna.tf32.f32 %0, %1;" : "=r"(r) : "f"(f));
    return r;
}
__device__ __forceinline__ float roundtf(float f) {
    return __uint_as_float(f2tf32(f));
}
__device__ __forceinline__ void mma_tf32(float* c, const uint32_t* a, const uint32_t* b) {
    asm volatile(
        "mma.sync.aligned.m16n8k8.row.col.f32.tf32.tf32.f32 "
        "{%0,%1,%2,%3}, {%4,%5,%6,%7}, {%8,%9}, {%0,%1,%2,%3};"
        : "+f"(c[0]), "+f"(c[1]), "+f"(c[2]), "+f"(c[3])
        : "r"(a[0]), "r"(a[1]), "r"(a[2]), "r"(a[3]), "r"(b[0]), "r"(b[1]));
}

// ---------------------------------------------------------------------------
// Pre-pass: round fp32 -> tf32 bit pattern. Grid-strided, 4 float4/thread.
// ---------------------------------------------------------------------------
__global__ __launch_bounds__(256)
void round_x_kernel(const float4* __restrict__ in, float4* __restrict__ out, int n4)
{
    int stride = gridDim.x * 256;
    for (int i = blockIdx.x * 256 + threadIdx.x; i < n4; i += stride) {
        float4 v = in[i];
        v.x = roundtf(v.x);
        v.y = roundtf(v.y);
        v.z = roundtf(v.z);
        v.w = roundtf(v.w);
        out[i] = v;
    }
}

// All four weights in one launch; blockIdx.y selects matrix.
__global__ __launch_bounds__(256)
void round_w_kernel(const float4* __restrict__ w0, const float4* __restrict__ w1,
                    const float4* __restrict__ w2, const float4* __restrict__ w3,
                    float4* __restrict__ out, int n4)
{
    const float4* in = (blockIdx.y == 0) ? w0 : (blockIdx.y == 1) ? w1
                     : (blockIdx.y == 2) ? w2 : w3;
    float4* dst = out + (size_t)blockIdx.y * n4;
    int stride = gridDim.x * 256;
    for (int i = blockIdx.x * 256 + threadIdx.x; i < n4; i += stride) {
        float4 v = in[i];
        v.x = roundtf(v.x);
        v.y = roundtf(v.y);
        v.z = roundtf(v.z);
        v.w = roundtf(v.w);
        dst[i] = v;
    }
}

// ---------------------------------------------------------------------------
// tf32 mma.sync GEMM core (BM=128 BN=128 BK=16, 256 thr, 3-stage cp.async).
// A_PRE: A pre-rounded (plain LDS). ROUND_OUT: round epilogue outputs to tf32.
// B always pre-rounded.
// ---------------------------------------------------------------------------
#define GKDIM 1024
#define GNDIM 1024
#define NKT 64
#define A_STRIDE 20
#define B_STRIDE 136
#define A_BYTES (128 * A_STRIDE * 4)
#define B_BYTES (16 * B_STRIDE * 4)
#define STAGE_BYTES (A_BYTES + B_BYTES)
#define GSTAGES 3
#define GEMM_SMEM (GSTAGES * STAGE_BYTES)

template <bool A_PRE, bool ROUND_OUT>
__device__ __forceinline__ void gemm_core(const float* __restrict__ A,
                                          const float* __restrict__ B,
                                          const float* __restrict__ bias,
                                          float* __restrict__ C,
                                          int m0, int n0, int useBias,
                                          char* dsmem)
{
    const int tid = threadIdx.x;
    const int wid = tid >> 5;
    const int lane = tid & 31;
    const int wm0 = (wid & 3) * 32;
    const int wn0 = (wid >> 2) * 64;
    const int qr = lane >> 2;
    const int qc = lane & 3;

    const uint32_t sbase = smem_to_u32(dsmem);

    float acc[2][8][4];
#pragma unroll
    for (int i = 0; i < 2; i++)
#pragma unroll
        for (int j = 0; j < 8; j++)
#pragma unroll
            for (int l = 0; l < 4; l++) acc[i][j][l] = 0.f;

    auto issue_stage = [&](int stage, int k0) {
        uint32_t aB = sbase + stage * STAGE_BYTES;
        uint32_t bB = aB + A_BYTES;
#pragma unroll
        for (int i = 0; i < 2; i++) {
            int idx = tid * 2 + i;
            int row = idx >> 2;
            int c4 = idx & 3;
            cp_async16(aB + row * (A_STRIDE * 4) + c4 * 16,
                       A + (size_t)(m0 + row) * GKDIM + k0 + c4 * 4);
            int krow = idx >> 5;
            int col = idx & 31;
            cp_async16(bB + krow * (B_STRIDE * 4) + col * 16,
                       B + (size_t)(k0 + krow) * GNDIM + n0 + col * 4);
        }
    };

    issue_stage(0, 0);
    CP_COMMIT();
    issue_stage(1, 16);
    CP_COMMIT();

    for (int kt = 0; kt < NKT; kt++) {
        int lt = kt + 2;
        if (lt < NKT) issue_stage(lt % GSTAGES, lt * 16);
        CP_COMMIT();
        CP_WAIT2();
        __syncthreads();

        const float* As = (const float*)(dsmem + (kt % GSTAGES) * STAGE_BYTES);
        const uint32_t* Asu = (const uint32_t*)As;
        const uint32_t* Bs = (const uint32_t*)(dsmem + (kt % GSTAGES) * STAGE_BYTES + A_BYTES);

#pragma unroll
        for (int ks = 0; ks < 2; ks++) {
            const int kb = ks * 8;
            uint32_t afr[2][4];
            uint32_t bfr[8][2];
#pragma unroll
            for (int mt = 0; mt < 2; mt++) {
                int mbase = wm0 + mt * 16;
                if (A_PRE) {
                    afr[mt][0] = Asu[(mbase + qr) * A_STRIDE + kb + qc];
                    afr[mt][1] = Asu[(mbase + qr + 8) * A_STRIDE + kb + qc];
                    afr[mt][2] = Asu[(mbase + qr) * A_STRIDE + kb + qc + 4];
                    afr[mt][3] = Asu[(mbase + qr + 8) * A_STRIDE + kb + qc + 4];
                } else {
                    afr[mt][0] = f2tf32(As[(mbase + qr) * A_STRIDE + kb + qc]);
                    afr[mt][1] = f2tf32(As[(mbase + qr + 8) * A_STRIDE + kb + qc]);
                    afr[mt][2] = f2tf32(As[(mbase + qr) * A_STRIDE + kb + qc + 4]);
                    afr[mt][3] = f2tf32(As[(mbase + qr + 8) * A_STRIDE + kb + qc + 4]);
                }
            }
#pragma unroll
            for (int nt = 0; nt < 8; nt++) {
                int nc = wn0 + nt * 8 + qr;
                bfr[nt][0] = Bs[(kb + qc) * B_STRIDE + nc];        // pre-rounded
                bfr[nt][1] = Bs[(kb + qc + 4) * B_STRIDE + nc];
            }
#pragma unroll
            for (int mt = 0; mt < 2; mt++)
#pragma unroll
                for (int nt = 0; nt < 8; nt++)
                    mma_tf32(acc[mt][nt], afr[mt], bfr[nt]);
        }
        __syncthreads();
    }

#pragma unroll
    for (int mt = 0; mt < 2; mt++) {
        int r0 = m0 + wm0 + mt * 16 + qr;
#pragma unroll
        for (int nt = 0; nt < 8; nt++) {
            int col = n0 + wn0 + nt * 8 + 2 * qc;
            float bx = 0.f, by = 0.f;
            if (useBias) {
                float2 bb = *(const float2*)(bias + col);
                bx = bb.x; by = bb.y;
            }
            float2 v0 = {acc[mt][nt][0] + bx, acc[mt][nt][1] + by};
            float2 v1 = {acc[mt][nt][2] + bx, acc[mt][nt][3] + by};
            if (ROUND_OUT) {
                v0.x = roundtf(v0.x); v0.y = roundtf(v0.y);
                v1.x = roundtf(v1.x); v1.y = roundtf(v1.y);
            }
            *(float2*)(C + (size_t)r0 * GNDIM + col) = v0;
            *(float2*)(C + (size_t)(r0 + 8) * GNDIM + col) = v1;
        }
    }
}

// Fused QKV: grid.x = 24 (3 weights x 8 N-tiles), grid.y = 64 (M-tiles)
__global__ __launch_bounds__(256)
void gemm_qkv_kernel(const float* __restrict__ x,
                     const float* __restrict__ Wq, const float* __restrict__ Wk,
                     const float* __restrict__ Wv,
                     float* __restrict__ q, float* __restrict__ k,
                     float* __restrict__ v)
{
    extern __shared__ char dsmem[];
    const int sel = blockIdx.x >> 3;
    const int n0 = (blockIdx.x & 7) * 128;
    const int m0 = blockIdx.y * 128;
    const float* B = (sel == 0) ? Wq : (sel == 1) ? Wk : Wv;
    float* C = (sel == 0) ? q : (sel == 1) ? k : v;
    gemm_core<true, true>(x, B, nullptr, C, m0, n0, 0, dsmem);   // rounded outputs
}

__global__ __launch_bounds__(256)
void gemm_tc_kernel(const float* __restrict__ A, const float* __restrict__ B,
                    const float* __restrict__ bias, float* __restrict__ C,
                    int useBias)
{
    extern __shared__ char dsmem[];
    gemm_core<false, false>(A, B, bias, C, blockIdx.y * 128, blockIdx.x * 128, useBias, dsmem);
}

// ---------------------------------------------------------------------------
// Flash attention (causal) with tf32 mma.sync. q/k/v pre-rounded in HBM ->
// Q/K/V fragment loads are plain LDS (no cvt). P-frags keep in-loop cvt.
// Br=128, Bc=64, 256 threads (8 warps). Single-buffered K/V (2 CTA/SM).
// ---------------------------------------------------------------------------
struct AttnSmem {
    float Qs[128][68];
    float Ks[64][68];
    float Vs[64][72];
    float Ps[128][68];
    float red_max[2][128];
    float red_sum[2][128];
    float row_scale[128];
    float row_inv[128];
};   // ~106 KB

__global__ __launch_bounds__(256, 2)
void attn_mma_kernel(const float* __restrict__ q, const float* __restrict__ k,
                     const float* __restrict__ v, float* __restrict__ out)
{
    extern __shared__ char smem_raw[];
    AttnSmem& sm = *reinterpret_cast<AttnSmem*>(smem_raw);

    const int tid = threadIdx.x;
    const int wid = tid >> 5;
    const int lane = tid & 31;
    const int qr = lane >> 2;
    const int qc = lane & 3;
    const int q0 = (gridDim.x - 1 - blockIdx.x) * 128;   // heavy tiles first
    const int bh = blockIdx.y;
    const int b = bh >> 4;
    const int h = bh & 15;

    const size_t base = (size_t)b * SEQ * DMODEL + (size_t)h * HDIM;

    // q pre-rounded; *0.125f is exponent-only -> still tf32-exact
    for (int idx = tid; idx < 2048; idx += 256) {
        int r = idx >> 4;
        int d4 = (idx & 15) << 2;
        float4 val = *(const float4*)(q + base + (size_t)(q0 + r) * DMODEL + d4);
        sm.Qs[r][d4 + 0] = val.x * 0.125f;
        sm.Qs[r][d4 + 1] = val.y * 0.125f;
        sm.Qs[r][d4 + 2] = val.z * 0.125f;
        sm.Qs[r][d4 + 3] = val.w * 0.125f;
    }

    auto load_k = [&](int k0) {
#pragma unroll
        for (int i = 0; i < 4; i++) {
            int idx = tid + i * 256;
            int c = idx >> 4;
            int d4 = (idx & 15) << 2;
            cp_async16(smem_to_u32(&sm.Ks[c][d4]),
                       k + base + (size_t)(k0 + c) * DMODEL + d4);
        }
    };
    auto load_v = [&](int k0) {
#pragma unroll
        for (int i = 0; i < 4; i++) {
            int idx = tid + i * 256;
            int c = idx >> 4;
            int d4 = (idx & 15) << 2;
            cp_async16(smem_to_u32(&sm.Vs[c][d4]),
                       v + base + (size_t)(k0 + c) * DMODEL + d4);
        }
    };

    const int srow = tid >> 1;
    const int shalf = tid & 1;
    const int sc0 = shalf * 32;
    float m_i = -INFINITY;
    float l_i = 0.f;

    float oacc[8][4];
#pragma unroll
    for (int nt = 0; nt < 8; nt++)
#pragma unroll
        for (int l = 0; l < 4; l++) oacc[nt][l] = 0.f;

    const int wm = (wid & 3) * 32;
    const int wn = (wid >> 2) * 32;

    const int nkt = (q0 >> 6) + 2;

    load_k(0);
    CP_COMMIT();

    for (int kt = 0; kt < nkt; kt++) {
        const int k0 = kt * 64;

        load_v(k0);
        CP_COMMIT();
        CP_WAIT0();
        __syncthreads();

        // ---- S = Q @ K^T (warp tile 32x32), plain LDS (pre-rounded) ----
        float sacc[2][4][4];
#pragma unroll
        for (int mt = 0; mt < 2; mt++)
#pragma unroll
            for (int nt = 0; nt < 4; nt++)
#pragma unroll
                for (int l = 0; l < 4; l++) sacc[mt][nt][l] = 0.f;

#pragma unroll
        for (int ks = 0; ks < 8; ks++) {
            const int kb = ks * 8;
            uint32_t afr[2][4];
            uint32_t bfr[4][2];
#pragma unroll
            for (int mt = 0; mt < 2; mt++) {
                int mbase = wm + mt * 16;
                afr[mt][0] = __float_as_uint(sm.Qs[mbase + qr][kb + qc]);
                afr[mt][1] = __float_as_uint(sm.Qs[mbase + qr + 8][kb + qc]);
                afr[mt][2] = __float_as_uint(sm.Qs[mbase + qr][kb + qc + 4]);
                afr[mt][3] = __float_as_uint(sm.Qs[mbase + qr + 8][kb + qc + 4]);
            }
#pragma unroll
            for (int nt = 0; nt < 4; nt++) {
                int nc = wn + nt * 8 + qr;
                bfr[nt][0] = __float_as_uint(sm.Ks[nc][kb + qc]);
                bfr[nt][1] = __float_as_uint(sm.Ks[nc][kb + qc + 4]);
            }
#pragma unroll
            for (int mt = 0; mt < 2; mt++)
#pragma unroll
                for (int nt = 0; nt < 4; nt++)
                    mma_tf32(sacc[mt][nt], afr[mt], bfr[nt]);
        }

        // Write S fragments to Ps
#pragma unroll
        for (int mt = 0; mt < 2; mt++) {
            int r0 = wm + mt * 16 + qr;
#pragma unroll
            for (int nt = 0; nt < 4; nt++) {
                int col = wn + nt * 8 + 2 * qc;
                *(float2*)&sm.Ps[r0][col]     = make_float2(sacc[mt][nt][0], sacc[mt][nt][1]);
                *(float2*)&sm.Ps[r0 + 8][col] = make_float2(sacc[mt][nt][2], sacc[mt][nt][3]);
            }
        }
        __syncthreads();

        // Prefetch K(kt+1) — overlaps softmax + PV
        if (kt + 1 < nkt) {
            load_k(k0 + 64);
            CP_COMMIT();
        }

        // ---- Online softmax (unchanged) ----
        {
            const int climit = q0 + srow - k0;
            const bool nomask = (climit >= sc0 + 31);
            float mloc = -INFINITY;
            if (nomask) {
#pragma unroll
                for (int c4 = 0; c4 < 8; c4++) {
                    float4 vv = *(const float4*)&sm.Ps[srow][sc0 + c4 * 4];
                    mloc = fmaxf(mloc, fmaxf(fmaxf(vv.x, vv.y), fmaxf(vv.z, vv.w)));
                }
            } else {
#pragma unroll
                for (int c4 = 0; c4 < 8; c4++) {
                    float4 vv = *(const float4*)&sm.Ps[srow][sc0 + c4 * 4];
                    int c = sc0 + c4 * 4;
                    if (c + 0 <= climit) mloc = fmaxf(mloc, vv.x);
                    if (c + 1 <= climit) mloc = fmaxf(mloc, vv.y);
                    if (c + 2 <= climit) mloc = fmaxf(mloc, vv.z);
                    if (c + 3 <= climit) mloc = fmaxf(mloc, vv.w);
                }
            }
            sm.red_max[shalf][srow] = mloc;
            __syncthreads();
            float mtile = fmaxf(sm.red_max[0][srow], sm.red_max[1][srow]);
            float mnew = fmaxf(m_i, mtile);
            float rs = __expf(m_i - mnew);
            if (shalf == 0) sm.row_scale[srow] = rs;

            float lsum = 0.f;
            if (nomask) {
#pragma unroll
                for (int c4 = 0; c4 < 8; c4++) {
                    float4 vv = *(float4*)&sm.Ps[srow][sc0 + c4 * 4];
                    vv.x = __expf(vv.x - mnew);
                    vv.y = __expf(vv.y - mnew);
                    vv.z = __expf(vv.z - mnew);
                    vv.w = __expf(vv.w - mnew);
                    lsum += vv.x + vv.y + vv.z + vv.w;
                    *(float4*)&sm.Ps[srow][sc0 + c4 * 4] = vv;
                }
            } else {
#pragma unroll
                for (int c4 = 0; c4 < 8; c4++) {
                    float4 vv = *(float4*)&sm.Ps[srow][sc0 + c4 * 4];
                    int c = sc0 + c4 * 4;
                    vv.x = (c + 0 <= climit) ? __expf(vv.x - mnew) : 0.f;
                    vv.y = (c + 1 <= climit) ? __expf(vv.y - mnew) : 0.f;
                    vv.z = (c + 2 <= climit) ? __expf(vv.z - mnew) : 0.f;
                    vv.w = (c + 3 <= climit) ? __expf(vv.w - mnew) : 0.f;
                    lsum += vv.x + vv.y + vv.z + vv.w;
                    *(float4*)&sm.Ps[srow][sc0 + c4 * 4] = vv;
                }
            }
            sm.red_sum[shalf][srow] = lsum;
            __syncthreads();
            l_i = l_i * rs + sm.red_sum[0][srow] + sm.red_sum[1][srow];
            m_i = mnew;
        }

        // ---- O = O*rs + P @ V (warp tile 16x64); V plain LDS, P cvt ----
        {
            const int mbase = wid * 16;
            float rs0 = sm.row_scale[mbase + qr];
            float rs1 = sm.row_scale[mbase + qr + 8];
#pragma unroll
            for (int nt = 0; nt < 8; nt++) {
                oacc[nt][0] *= rs0; oacc[nt][1] *= rs0;
                oacc[nt][2] *= rs1; oacc[nt][3] *= rs1;
            }
#pragma unroll
            for (int ks = 0; ks < 8; ks++) {
                const int kb = ks * 8;
                uint32_t afr[4];
                afr[0] = f2tf32(sm.Ps[mbase + qr][kb + qc]);
                afr[1] = f2tf32(sm.Ps[mbase + qr + 8][kb + qc]);
                afr[2] = f2tf32(sm.Ps[mbase + qr][kb + qc + 4]);
                afr[3] = f2tf32(sm.Ps[mbase + qr + 8][kb + qc + 4]);
                uint32_t bfr[8][2];
#pragma unroll
                for (int nt = 0; nt < 8; nt++) {
                    int nc = nt * 8 + qr;
                    bfr[nt][0] = __float_as_uint(sm.Vs[kb + qc][nc]);
                    bfr[nt][1] = __float_as_uint(sm.Vs[kb + qc + 4][nc]);
                }
#pragma unroll
                for (int nt = 0; nt < 8; nt++)
                    mma_tf32(oacc[nt], afr, bfr[nt]);
            }
        }
        __syncthreads();
    }

    // Final normalization
    if (shalf == 0) sm.row_inv[srow] = 1.f / l_i;
    __syncthreads();

    {
        const int mbase = wid * 16;
        float inv0 = sm.row_inv[mbase + qr];
        float inv1 = sm.row_inv[mbase + qr + 8];
        size_t r0 = base + (size_t)(q0 + mbase + qr) * DMODEL;
        size_t r1 = base + (size_t)(q0 + mbase + qr + 8) * DMODEL;
#pragma unroll
        for (int nt = 0; nt < 8; nt++) {
            int col = nt * 8 + 2 * qc;
            *(float2*)(out + r0 + col) = make_float2(oacc[nt][0] * inv0, oacc[nt][1] * inv0);
            *(float2*)(out + r1 + col) = make_float2(oacc[nt][2] * inv1, oacc[nt][3] * inv1);
        }
    }
}

// ---------------------------------------------------------------------------
// Launch
// ---------------------------------------------------------------------------
extern "C" void kernel_launch(void* const* d_in, const int* in_sizes, int n_in,
                              void* d_out, int out_size)
{
    const float* x  = (const float*)d_in[0];
    const float* Wq = (const float*)d_in[1];
    const float* Wk = (const float*)d_in[2];
    const float* Wv = (const float*)d_in[3];
    const float* Wo = (const float*)d_in[4];
    const float* bo = (const float*)d_in[5];
    float* out = (float*)d_out;

    float *qp, *kp, *vp, *ap, *xr, *wr;
    cudaGetSymbolAddress((void**)&qp, g_q);
    cudaGetSymbolAddress((void**)&kp, g_k);
    cudaGetSymbolAddress((void**)&vp, g_v);
    cudaGetSymbolAddress((void**)&ap, g_attn);
    cudaGetSymbolAddress((void**)&xr, g_xr);
    cudaGetSymbolAddress((void**)&wr, g_wr);
    float* wrq = wr;
    float* wro = wr + 3 * DMODEL * DMODEL;

    cudaFuncSetAttribute(gemm_qkv_kernel, cudaFuncAttributeMaxDynamicSharedMemorySize, GEMM_SMEM);
    cudaFuncSetAttribute(gemm_tc_kernel, cudaFuncAttributeMaxDynamicSharedMemorySize, GEMM_SMEM);
    cudaFuncSetAttribute(attn_mma_kernel, cudaFuncAttributeMaxDynamicSharedMemorySize,
                         (int)sizeof(AttnSmem));

    // Pre-round x and weights (grid-strided, 4 float4/thread)
    const int XN4 = MTOT * DMODEL / 4;
    const int WN4 = DMODEL * DMODEL / 4;
    round_x_kernel<<<XN4 / (256 * 4), 256>>>((const float4*)x, (float4*)xr, XN4);
    dim3 wgrid(WN4 / (256 * 4), 4);
    round_w_kernel<<<wgrid, 256>>>((const float4*)Wq, (const float4*)Wk,
                                   (const float4*)Wv, (const float4*)Wo,
                                   (float4*)wr, WN4);

    // Fused QKV projections (zero-cvt inner loop, rounded outputs)
    dim3 qkvgrid(24, MTOT / 128);
    gemm_qkv_kernel<<<qkvgrid, 256, GEMM_SMEM>>>(xr, wrq, wrq + WN4 * 4, wrq + 2 * WN4 * 4,
                                                 qp, kp, vp);

    // Causal flash attention (cvt-free Q/K/V fragment loads)
    dim3 agrid(SEQ / 128, BATCH * NHEADS);
    attn_mma_kernel<<<agrid, 256, sizeof(AttnSmem)>>>(qp, kp, vp, ap);

    // Output projection + bias (A cvt in-loop)
    dim3 ggrid(GNDIM / 128, MTOT / 128);
    gemm_tc_kernel<<<ggrid, 256, GEMM_SMEM>>>(ap, wro, bo, out, 1);
}

// round 13
// speedup vs baseline: 1.6172x; 1.0428x over previous
#include <cuda_runtime.h>
#include <cuda_bf16.h>
#include <math.h>
#include <stdint.h>

// Problem constants
#define BATCH 4
#define SEQ 2048
#define DMODEL 1024
#define NHEADS 16
#define HDIM 64
#define MTOT (BATCH * SEQ)          // 8192 rows

// ---------------------------------------------------------------------------
// Scratch (device globals: allocation-free, graph-safe)
// ---------------------------------------------------------------------------
__device__ float g_q[MTOT * DMODEL];
__device__ float g_k[MTOT * DMODEL];
__device__ float g_v[MTOT * DMODEL];
__device__ float g_attn[MTOT * DMODEL];
__device__ float g_xr[MTOT * DMODEL];        // tf32-rounded x
__device__ float g_wr[4][DMODEL * DMODEL];   // tf32-rounded Wq,Wk,Wv,Wo

// ---------------------------------------------------------------------------
// Helpers
// ---------------------------------------------------------------------------
__device__ __forceinline__ uint32_t smem_to_u32(const void* p) {
    uint32_t a;
    asm("{ .reg .u64 t; cvta.to.shared.u64 t, %1; cvt.u32.u64 %0, t; }"
        : "=r"(a) : "l"(p));
    return a;
}
__device__ __forceinline__ void cp_async16(uint32_t dst, const void* src) {
    asm volatile("cp.async.cg.shared.global [%0], [%1], 16;" :: "r"(dst), "l"(src));
}
#define CP_COMMIT() asm volatile("cp.async.commit_group;" ::: "memory")
#define CP_WAIT1()  asm volatile("cp.async.wait_group 1;" ::: "memory")
#define CP_WAIT3()  asm volatile("cp.async.wait_group 3;" ::: "memory")

__device__ __forceinline__ uint32_t f2tf32(float f) {
    uint32_t r;
    asm("cvt.rna.tf32.f32 %0, %1;" : "=r"(r) : "f"(f));
    return r;
}
__device__ __forceinline__ float roundtf(float f) {
    return __uint_as_float(f2tf32(f));
}
__device__ __forceinline__ void mma_tf32(float* c, const uint32_t* a, const uint32_t* b) {
    asm volatile(
        "mma.sync.aligned.m16n8k8.row.col.f32.tf32.tf32.f32 "
        "{%0,%1,%2,%3}, {%4,%5,%6,%7}, {%8,%9}, {%0,%1,%2,%3};"
        : "+f"(c[0]), "+f"(c[1]), "+f"(c[2]), "+f"(c[3])
        : "r"(a[0]), "r"(a[1]), "r"(a[2]), "r"(a[3]), "r"(b[0]), "r"(b[1]));
}

// ---------------------------------------------------------------------------
// Pre-pass: round fp32 -> tf32 bit pattern. Grid-strided, 4 float4/thread.
// ---------------------------------------------------------------------------
__global__ __launch_bounds__(256)
void round_x_kernel(const float4* __restrict__ in, float4* __restrict__ out, int n4)
{
    int stride = gridDim.x * 256;
    for (int i = blockIdx.x * 256 + threadIdx.x; i < n4; i += stride) {
        float4 v = in[i];
        v.x = roundtf(v.x);
        v.y = roundtf(v.y);
        v.z = roundtf(v.z);
        v.w = roundtf(v.w);
        out[i] = v;
    }
}

__global__ __launch_bounds__(256)
void round_w_kernel(const float4* __restrict__ w0, const float4* __restrict__ w1,
                    const float4* __restrict__ w2, const float4* __restrict__ w3,
                    float4* __restrict__ out, int n4)
{
    const float4* in = (blockIdx.y == 0) ? w0 : (blockIdx.y == 1) ? w1
                     : (blockIdx.y == 2) ? w2 : w3;
    float4* dst = out + (size_t)blockIdx.y * n4;
    int stride = gridDim.x * 256;
    for (int i = blockIdx.x * 256 + threadIdx.x; i < n4; i += stride) {
        float4 v = in[i];
        v.x = roundtf(v.x);
        v.y = roundtf(v.y);
        v.z = roundtf(v.z);
        v.w = roundtf(v.w);
        dst[i] = v;
    }
}

// ---------------------------------------------------------------------------
// tf32 mma.sync GEMM core (BM=128 BN=128 BK=16, 256 thr, 4-stage cp.async).
// A_PRE: A pre-rounded (plain LDS). ROUND_OUT: round epilogue outputs to tf32.
// B always pre-rounded.
// ---------------------------------------------------------------------------
#define GKDIM 1024
#define GNDIM 1024
#define NKT 64
#define A_STRIDE 20
#define B_STRIDE 136
#define A_BYTES (128 * A_STRIDE * 4)
#define B_BYTES (16 * B_STRIDE * 4)
#define STAGE_BYTES (A_BYTES + B_BYTES)
#define GSTAGES 4
#define GEMM_SMEM (GSTAGES * STAGE_BYTES)   // 75776

template <bool A_PRE, bool ROUND_OUT>
__device__ __forceinline__ void gemm_core(const float* __restrict__ A,
                                          const float* __restrict__ B,
                                          const float* __restrict__ bias,
                                          float* __restrict__ C,
                                          int m0, int n0, int useBias,
                                          char* dsmem)
{
    const int tid = threadIdx.x;
    const int wid = tid >> 5;
    const int lane = tid & 31;
    const int wm0 = (wid & 3) * 32;
    const int wn0 = (wid >> 2) * 64;
    const int qr = lane >> 2;
    const int qc = lane & 3;

    const uint32_t sbase = smem_to_u32(dsmem);

    float acc[2][8][4];
#pragma unroll
    for (int i = 0; i < 2; i++)
#pragma unroll
        for (int j = 0; j < 8; j++)
#pragma unroll
            for (int l = 0; l < 4; l++) acc[i][j][l] = 0.f;

    auto issue_stage = [&](int stage, int k0) {
        uint32_t aB = sbase + stage * STAGE_BYTES;
        uint32_t bB = aB + A_BYTES;
#pragma unroll
        for (int i = 0; i < 2; i++) {
            int idx = tid * 2 + i;
            int row = idx >> 2;
            int c4 = idx & 3;
            cp_async16(aB + row * (A_STRIDE * 4) + c4 * 16,
                       A + (size_t)(m0 + row) * GKDIM + k0 + c4 * 4);
            int krow = idx >> 5;
            int col = idx & 31;
            cp_async16(bB + krow * (B_STRIDE * 4) + col * 16,
                       B + (size_t)(k0 + krow) * GNDIM + n0 + col * 4);
        }
    };

    issue_stage(0, 0);
    CP_COMMIT();
    issue_stage(1, 16);
    CP_COMMIT();
    issue_stage(2, 32);
    CP_COMMIT();

    for (int kt = 0; kt < NKT; kt++) {
        int lt = kt + 3;
        if (lt < NKT) issue_stage(lt & 3, lt * 16);
        CP_COMMIT();
        CP_WAIT3();
        __syncthreads();

        const float* As = (const float*)(dsmem + (kt & 3) * STAGE_BYTES);
        const uint32_t* Asu = (const uint32_t*)As;
        const uint32_t* Bs = (const uint32_t*)(dsmem + (kt & 3) * STAGE_BYTES + A_BYTES);

#pragma unroll
        for (int ks = 0; ks < 2; ks++) {
            const int kb = ks * 8;
            uint32_t afr[2][4];
            uint32_t bfr[8][2];
#pragma unroll
            for (int mt = 0; mt < 2; mt++) {
                int mbase = wm0 + mt * 16;
                if (A_PRE) {
                    afr[mt][0] = Asu[(mbase + qr) * A_STRIDE + kb + qc];
                    afr[mt][1] = Asu[(mbase + qr + 8) * A_STRIDE + kb + qc];
                    afr[mt][2] = Asu[(mbase + qr) * A_STRIDE + kb + qc + 4];
                    afr[mt][3] = Asu[(mbase + qr + 8) * A_STRIDE + kb + qc + 4];
                } else {
                    afr[mt][0] = f2tf32(As[(mbase + qr) * A_STRIDE + kb + qc]);
                    afr[mt][1] = f2tf32(As[(mbase + qr + 8) * A_STRIDE + kb + qc]);
                    afr[mt][2] = f2tf32(As[(mbase + qr) * A_STRIDE + kb + qc + 4]);
                    afr[mt][3] = f2tf32(As[(mbase + qr + 8) * A_STRIDE + kb + qc + 4]);
                }
            }
#pragma unroll
            for (int nt = 0; nt < 8; nt++) {
                int nc = wn0 + nt * 8 + qr;
                bfr[nt][0] = Bs[(kb + qc) * B_STRIDE + nc];        // pre-rounded
                bfr[nt][1] = Bs[(kb + qc + 4) * B_STRIDE + nc];
            }
#pragma unroll
            for (int mt = 0; mt < 2; mt++)
#pragma unroll
                for (int nt = 0; nt < 8; nt++)
                    mma_tf32(acc[mt][nt], afr[mt], bfr[nt]);
        }
        __syncthreads();
    }

#pragma unroll
    for (int mt = 0; mt < 2; mt++) {
        int r0 = m0 + wm0 + mt * 16 + qr;
#pragma unroll
        for (int nt = 0; nt < 8; nt++) {
            int col = n0 + wn0 + nt * 8 + 2 * qc;
            float bx = 0.f, by = 0.f;
            if (useBias) {
                float2 bb = *(const float2*)(bias + col);
                bx = bb.x; by = bb.y;
            }
            float2 v0 = {acc[mt][nt][0] + bx, acc[mt][nt][1] + by};
            float2 v1 = {acc[mt][nt][2] + bx, acc[mt][nt][3] + by};
            if (ROUND_OUT) {
                v0.x = roundtf(v0.x); v0.y = roundtf(v0.y);
                v1.x = roundtf(v1.x); v1.y = roundtf(v1.y);
            }
            *(float2*)(C + (size_t)r0 * GNDIM + col) = v0;
            *(float2*)(C + (size_t)(r0 + 8) * GNDIM + col) = v1;
        }
    }
}

// Fused QKV: grid.x = 24 (3 weights x 8 N-tiles), grid.y = 64 (M-tiles)
__global__ __launch_bounds__(256)
void gemm_qkv_kernel(const float* __restrict__ x,
                     const float* __restrict__ Wq, const float* __restrict__ Wk,
                     const float* __restrict__ Wv,
                     float* __restrict__ q, float* __restrict__ k,
                     float* __restrict__ v)
{
    extern __shared__ char dsmem[];
    const int sel = blockIdx.x >> 3;
    const int n0 = (blockIdx.x & 7) * 128;
    const int m0 = blockIdx.y * 128;
    const float* B = (sel == 0) ? Wq : (sel == 1) ? Wk : Wv;
    float* C = (sel == 0) ? q : (sel == 1) ? k : v;
    gemm_core<true, true>(x, B, nullptr, C, m0, n0, 0, dsmem);
}

__global__ __launch_bounds__(256)
void gemm_tc_kernel(const float* __restrict__ A, const float* __restrict__ B,
                    const float* __restrict__ bias, float* __restrict__ C,
                    int useBias)
{
    extern __shared__ char dsmem[];
    gemm_core<false, false>(A, B, bias, C, blockIdx.y * 128, blockIdx.x * 128, useBias, dsmem);
}

// ---------------------------------------------------------------------------
// Flash attention (causal) with tf32 mma.sync. q/k/v pre-rounded in HBM.
// Br=128, Bc=64, 256 threads (8 warps). Single-buffered K/V (2 CTA/SM).
// Split-group cp.async pipeline: K waited before S, V waited before PV;
// V(kt+1) issued after PV(kt) completes. shfl-based softmax reductions.
// ---------------------------------------------------------------------------
struct AttnSmem {
    float Qs[128][68];
    float Ks[64][68];
    float Vs[64][72];
    float Ps[128][68];
    float row_scale[128];
    float row_inv[128];
};

__global__ __launch_bounds__(256, 2)
void attn_mma_kernel(const float* __restrict__ q, const float* __restrict__ k,
                     const float* __restrict__ v, float* __restrict__ out)
{
    extern __shared__ char smem_raw[];
    AttnSmem& sm = *reinterpret_cast<AttnSmem*>(smem_raw);

    const int tid = threadIdx.x;
    const int wid = tid >> 5;
    const int lane = tid & 31;
    const int qr = lane >> 2;
    const int qc = lane & 3;
    const int q0 = (gridDim.x - 1 - blockIdx.x) * 128;   // heavy tiles first
    const int bh = blockIdx.y;
    const int b = bh >> 4;
    const int h = bh & 15;

    const size_t base = (size_t)b * SEQ * DMODEL + (size_t)h * HDIM;

    // q pre-rounded; *0.125f is exponent-only -> still tf32-exact
    for (int idx = tid; idx < 2048; idx += 256) {
        int r = idx >> 4;
        int d4 = (idx & 15) << 2;
        float4 val = *(const float4*)(q + base + (size_t)(q0 + r) * DMODEL + d4);
        sm.Qs[r][d4 + 0] = val.x * 0.125f;
        sm.Qs[r][d4 + 1] = val.y * 0.125f;
        sm.Qs[r][d4 + 2] = val.z * 0.125f;
        sm.Qs[r][d4 + 3] = val.w * 0.125f;
    }

    auto load_k = [&](int k0) {
#pragma unroll
        for (int i = 0; i < 4; i++) {
            int idx = tid + i * 256;
            int c = idx >> 4;
            int d4 = (idx & 15) << 2;
            cp_async16(smem_to_u32(&sm.Ks[c][d4]),
                       k + base + (size_t)(k0 + c) * DMODEL + d4);
        }
    };
    auto load_v = [&](int k0) {
#pragma unroll
        for (int i = 0; i < 4; i++) {
            int idx = tid + i * 256;
            int c = idx >> 4;
            int d4 = (idx & 15) << 2;
            cp_async16(smem_to_u32(&sm.Vs[c][d4]),
                       v + base + (size_t)(k0 + c) * DMODEL + d4);
        }
    };

    const int srow = tid >> 1;
    const int shalf = tid & 1;
    const int sc0 = shalf * 32;
    float m_i = -INFINITY;
    float l_i = 0.f;

    float oacc[8][4];
#pragma unroll
    for (int nt = 0; nt < 8; nt++)
#pragma unroll
        for (int l = 0; l < 4; l++) oacc[nt][l] = 0.f;

    const int wm = (wid & 3) * 32;
    const int wn = (wid >> 2) * 32;

    const int nkt = (q0 >> 6) + 2;

    // Pipeline prologue: groups in FIFO order {K0, V0}
    load_k(0);
    CP_COMMIT();
    load_v(0);
    CP_COMMIT();

    for (int kt = 0; kt < nkt; kt++) {
        const int k0 = kt * 64;

        CP_WAIT1();               // K(kt) ready; V(kt) may still be in flight
        __syncthreads();

        // ---- S = Q @ K^T (warp tile 32x32), plain LDS (pre-rounded) ----
        float sacc[2][4][4];
#pragma unroll
        for (int mt = 0; mt < 2; mt++)
#pragma unroll
            for (int nt = 0; nt < 4; nt++)
#pragma unroll
                for (int l = 0; l < 4; l++) sacc[mt][nt][l] = 0.f;

#pragma unroll
        for (int ks = 0; ks < 8; ks++) {
            const int kb = ks * 8;
            uint32_t afr[2][4];
            uint32_t bfr[4][2];
#pragma unroll
            for (int mt = 0; mt < 2; mt++) {
                int mbase = wm + mt * 16;
                afr[mt][0] = __float_as_uint(sm.Qs[mbase + qr][kb + qc]);
                afr[mt][1] = __float_as_uint(sm.Qs[mbase + qr + 8][kb + qc]);
                afr[mt][2] = __float_as_uint(sm.Qs[mbase + qr][kb + qc + 4]);
                afr[mt][3] = __float_as_uint(sm.Qs[mbase + qr + 8][kb + qc + 4]);
            }
#pragma unroll
            for (int nt = 0; nt < 4; nt++) {
                int nc = wn + nt * 8 + qr;
                bfr[nt][0] = __float_as_uint(sm.Ks[nc][kb + qc]);
                bfr[nt][1] = __float_as_uint(sm.Ks[nc][kb + qc + 4]);
            }
#pragma unroll
            for (int mt = 0; mt < 2; mt++)
#pragma unroll
                for (int nt = 0; nt < 4; nt++)
                    mma_tf32(sacc[mt][nt], afr[mt], bfr[nt]);
        }

        // Write S fragments to Ps
#pragma unroll
        for (int mt = 0; mt < 2; mt++) {
            int r0 = wm + mt * 16 + qr;
#pragma unroll
            for (int nt = 0; nt < 4; nt++) {
                int col = wn + nt * 8 + 2 * qc;
                *(float2*)&sm.Ps[r0][col]     = make_float2(sacc[mt][nt][0], sacc[mt][nt][1]);
                *(float2*)&sm.Ps[r0 + 8][col] = make_float2(sacc[mt][nt][2], sacc[mt][nt][3]);
            }
        }
        __syncthreads();          // Ps complete; Ks free

        // Prefetch K(kt+1) — hidden behind softmax + PV
        if (kt + 1 < nkt) load_k(k0 + 64);
        CP_COMMIT();

        // ---- Online softmax (shfl pair-reduction, no extra barriers) ----
        {
            const int climit = q0 + srow - k0;
            const bool nomask = (climit >= sc0 + 31);
            float mloc = -INFINITY;
            if (nomask) {
#pragma unroll
                for (int c4 = 0; c4 < 8; c4++) {
                    float4 vv = *(const float4*)&sm.Ps[srow][sc0 + c4 * 4];
                    mloc = fmaxf(mloc, fmaxf(fmaxf(vv.x, vv.y), fmaxf(vv.z, vv.w)));
                }
            } else {
#pragma unroll
                for (int c4 = 0; c4 < 8; c4++) {
                    float4 vv = *(const float4*)&sm.Ps[srow][sc0 + c4 * 4];
                    int c = sc0 + c4 * 4;
                    if (c + 0 <= climit) mloc = fmaxf(mloc, vv.x);
                    if (c + 1 <= climit) mloc = fmaxf(mloc, vv.y);
                    if (c + 2 <= climit) mloc = fmaxf(mloc, vv.z);
                    if (c + 3 <= climit) mloc = fmaxf(mloc, vv.w);
                }
            }
            float mo = __shfl_xor_sync(0xffffffffu, mloc, 1);
            float mtile = fmaxf(mloc, mo);
            float mnew = fmaxf(m_i, mtile);
            float rs = __expf(m_i - mnew);
            if (shalf == 0) sm.row_scale[srow] = rs;

            float lsum = 0.f;
            if (nomask) {
#pragma unroll
                for (int c4 = 0; c4 < 8; c4++) {
                    float4 vv = *(float4*)&sm.Ps[srow][sc0 + c4 * 4];
                    vv.x = __expf(vv.x - mnew);
                    vv.y = __expf(vv.y - mnew);
                    vv.z = __expf(vv.z - mnew);
                    vv.w = __expf(vv.w - mnew);
                    lsum += vv.x + vv.y + vv.z + vv.w;
                    *(float4*)&sm.Ps[srow][sc0 + c4 * 4] = vv;
                }
            } else {
#pragma unroll
                for (int c4 = 0; c4 < 8; c4++) {
                    float4 vv = *(float4*)&sm.Ps[srow][sc0 + c4 * 4];
                    int c = sc0 + c4 * 4;
                    vv.x = (c + 0 <= climit) ? __expf(vv.x - mnew) : 0.f;
                    vv.y = (c + 1 <= climit) ? __expf(vv.y - mnew) : 0.f;
                    vv.z = (c + 2 <= climit) ? __expf(vv.z - mnew) : 0.f;
                    vv.w = (c + 3 <= climit) ? __expf(vv.w - mnew) : 0.f;
                    lsum += vv.x + vv.y + vv.z + vv.w;
                    *(float4*)&sm.Ps[srow][sc0 + c4 * 4] = vv;
                }
            }
            float lo = __shfl_xor_sync(0xffffffffu, lsum, 1);
            l_i = l_i * rs + lsum + lo;
            m_i = mnew;
        }

        CP_WAIT1();               // V(kt) ready (K(kt+1) still pending)
        __syncthreads();          // Ps/row_scale visible + V chunks visible

        // ---- O = O*rs + P @ V (warp tile 16x64); V plain LDS, P cvt ----
        {
            const int mbase = wid * 16;
            float rs0 = sm.row_scale[mbase + qr];
            float rs1 = sm.row_scale[mbase + qr + 8];
#pragma unroll
            for (int nt = 0; nt < 8; nt++) {
                oacc[nt][0] *= rs0; oacc[nt][1] *= rs0;
                oacc[nt][2] *= rs1; oacc[nt][3] *= rs1;
            }
#pragma unroll
            for (int ks = 0; ks < 8; ks++) {
                const int kb = ks * 8;
                uint32_t afr[4];
                afr[0] = f2tf32(sm.Ps[mbase + qr][kb + qc]);
                afr[1] = f2tf32(sm.Ps[mbase + qr + 8][kb + qc]);
                afr[2] = f2tf32(sm.Ps[mbase + qr][kb + qc + 4]);
                afr[3] = f2tf32(sm.Ps[mbase + qr + 8][kb + qc + 4]);
                uint32_t bfr[8][2];
#pragma unroll
                for (int nt = 0; nt < 8; nt++) {
                    int nc = nt * 8 + qr;
                    bfr[nt][0] = __float_as_uint(sm.Vs[kb + qc][nc]);
                    bfr[nt][1] = __float_as_uint(sm.Vs[kb + qc + 4][nc]);
                }
#pragma unroll
                for (int nt = 0; nt < 8; nt++)
                    mma_tf32(oacc[nt], afr, bfr[nt]);
            }
        }
        __syncthreads();          // all warps done reading Vs(kt)/Ps

        // Issue V(kt+1) — hidden behind next S-phase + softmax
        if (kt + 1 < nkt) load_v(k0 + 64);
        CP_COMMIT();
    }

    // Final normalization
    if (shalf == 0) sm.row_inv[srow] = 1.f / l_i;
    __syncthreads();

    {
        const int mbase = wid * 16;
        float inv0 = sm.row_inv[mbase + qr];
        float inv1 = sm.row_inv[mbase + qr + 8];
        size_t r0 = base + (size_t)(q0 + mbase + qr) * DMODEL;
        size_t r1 = base + (size_t)(q0 + mbase + qr + 8) * DMODEL;
#pragma unroll
        for (int nt = 0; nt < 8; nt++) {
            int col = nt * 8 + 2 * qc;
            *(float2*)(out + r0 + col) = make_float2(oacc[nt][0] * inv0, oacc[nt][1] * inv0);
            *(float2*)(out + r1 + col) = make_float2(oacc[nt][2] * inv1, oacc[nt][3] * inv1);
        }
    }
}

// ---------------------------------------------------------------------------
// Launch
// ---------------------------------------------------------------------------
extern "C" void kernel_launch(void* const* d_in, const int* in_sizes, int n_in,
                              void* d_out, int out_size)
{
    const float* x  = (const float*)d_in[0];
    const float* Wq = (const float*)d_in[1];
    const float* Wk = (const float*)d_in[2];
    const float* Wv = (const float*)d_in[3];
    const float* Wo = (const float*)d_in[4];
    const float* bo = (const float*)d_in[5];
    float* out = (float*)d_out;

    float *qp, *kp, *vp, *ap, *xr, *wr;
    cudaGetSymbolAddress((void**)&qp, g_q);
    cudaGetSymbolAddress((void**)&kp, g_k);
    cudaGetSymbolAddress((void**)&vp, g_v);
    cudaGetSymbolAddress((void**)&ap, g_attn);
    cudaGetSymbolAddress((void**)&xr, g_xr);
    cudaGetSymbolAddress((void**)&wr, g_wr);
    float* wrq = wr;
    float* wro = wr + 3 * DMODEL * DMODEL;

    cudaFuncSetAttribute(gemm_qkv_kernel, cudaFuncAttributeMaxDynamicSharedMemorySize, GEMM_SMEM);
    cudaFuncSetAttribute(gemm_tc_kernel, cudaFuncAttributeMaxDynamicSharedMemorySize, GEMM_SMEM);
    cudaFuncSetAttribute(attn_mma_kernel, cudaFuncAttributeMaxDynamicSharedMemorySize,
                         (int)sizeof(AttnSmem));

    // Pre-round x and weights (grid-strided, 4 float4/thread)
    const int XN4 = MTOT * DMODEL / 4;
    const int WN4 = DMODEL * DMODEL / 4;
    round_x_kernel<<<XN4 / (256 * 4), 256>>>((const float4*)x, (float4*)xr, XN4);
    dim3 wgrid(WN4 / (256 * 4), 4);
    round_w_kernel<<<wgrid, 256>>>((const float4*)Wq, (const float4*)Wk,
                                   (const float4*)Wv, (const float4*)Wo,
                                   (float4*)wr, WN4);

    // Fused QKV projections (zero-cvt inner loop, rounded outputs)
    dim3 qkvgrid(24, MTOT / 128);
    gemm_qkv_kernel<<<qkvgrid, 256, GEMM_SMEM>>>(xr, wrq, wrq + WN4 * 4, wrq + 2 * WN4 * 4,
                                                 qp, kp, vp);

    // Causal flash attention (split-group pipeline)
    dim3 agrid(SEQ / 128, BATCH * NHEADS);
    attn_mma_kernel<<<agrid, 256, sizeof(AttnSmem)>>>(qp, kp, vp, ap);

    // Output projection + bias (A cvt in-loop)
    dim3 ggrid(GNDIM / 128, MTOT / 128);
    gemm_tc_kernel<<<ggrid, 256, GEMM_SMEM>>>(ap, wro, bo, out, 1);
}

// round 15
// speedup vs baseline: 1.7072x; 1.0557x over previous
#include <cuda_runtime.h>
#include <cuda_bf16.h>
#include <math.h>
#include <stdint.h>

// Problem constants
#define BATCH 4
#define SEQ 2048
#define DMODEL 1024
#define NHEADS 16
#define HDIM 64
#define MTOT (BATCH * SEQ)          // 8192 rows

// ---------------------------------------------------------------------------
// Scratch (device globals: allocation-free, graph-safe)
// ---------------------------------------------------------------------------
__device__ float g_q[MTOT * DMODEL];
__device__ float g_k[MTOT * DMODEL];
__device__ float g_v[MTOT * DMODEL];
__device__ float g_attn[MTOT * DMODEL];
__device__ float g_xr[MTOT * DMODEL];        // tf32-rounded x
__device__ float g_wr[4][DMODEL * DMODEL];   // tf32-rounded Wq,Wk,Wv,Wo

// ---------------------------------------------------------------------------
// Helpers
// ---------------------------------------------------------------------------
__device__ __forceinline__ uint32_t smem_to_u32(const void* p) {
    uint32_t a;
    asm("{ .reg .u64 t; cvta.to.shared.u64 t, %1; cvt.u32.u64 %0, t; }"
        : "=r"(a) : "l"(p));
    return a;
}
__device__ __forceinline__ void cp_async16(uint32_t dst, const void* src) {
    asm volatile("cp.async.cg.shared.global [%0], [%1], 16;" :: "r"(dst), "l"(src));
}
#define CP_COMMIT() asm volatile("cp.async.commit_group;" ::: "memory")
#define CP_WAIT1()  asm volatile("cp.async.wait_group 1;" ::: "memory")
#define CP_WAIT3()  asm volatile("cp.async.wait_group 3;" ::: "memory")

__device__ __forceinline__ uint32_t f2tf32(float f) {
    uint32_t r;
    asm("cvt.rna.tf32.f32 %0, %1;" : "=r"(r) : "f"(f));
    return r;
}
__device__ __forceinline__ float roundtf(float f) {
    return __uint_as_float(f2tf32(f));
}
__device__ __forceinline__ void mma_tf32(float* c, const uint32_t* a, const uint32_t* b) {
    asm volatile(
        "mma.sync.aligned.m16n8k8.row.col.f32.tf32.tf32.f32 "
        "{%0,%1,%2,%3}, {%4,%5,%6,%7}, {%8,%9}, {%0,%1,%2,%3};"
        : "+f"(c[0]), "+f"(c[1]), "+f"(c[2]), "+f"(c[3])
        : "r"(a[0]), "r"(a[1]), "r"(a[2]), "r"(a[3]), "r"(b[0]), "r"(b[1]));
}

// ---------------------------------------------------------------------------
// Pre-pass: round fp32 -> tf32 bit pattern. Grid-strided, 4 float4/thread.
// ---------------------------------------------------------------------------
__global__ __launch_bounds__(256)
void round_x_kernel(const float4* __restrict__ in, float4* __restrict__ out, int n4)
{
    int stride = gridDim.x * 256;
    for (int i = blockIdx.x * 256 + threadIdx.x; i < n4; i += stride) {
        float4 v = in[i];
        v.x = roundtf(v.x);
        v.y = roundtf(v.y);
        v.z = roundtf(v.z);
        v.w = roundtf(v.w);
        out[i] = v;
    }
}

__global__ __launch_bounds__(256)
void round_w_kernel(const float4* __restrict__ w0, const float4* __restrict__ w1,
                    const float4* __restrict__ w2, const float4* __restrict__ w3,
                    float4* __restrict__ out, int n4)
{
    const float4* in = (blockIdx.y == 0) ? w0 : (blockIdx.y == 1) ? w1
                     : (blockIdx.y == 2) ? w2 : w3;
    float4* dst = out + (size_t)blockIdx.y * n4;
    int stride = gridDim.x * 256;
    for (int i = blockIdx.x * 256 + threadIdx.x; i < n4; i += stride) {
        float4 v = in[i];
        v.x = roundtf(v.x);
        v.y = roundtf(v.y);
        v.z = roundtf(v.z);
        v.w = roundtf(v.w);
        dst[i] = v;
    }
}

// ---------------------------------------------------------------------------
// tf32 mma.sync GEMM core (BM=128 BN=128 BK=16, 256 thr, 4-stage cp.async).
// A_PRE: A pre-rounded (plain LDS). ROUND_OUT: round epilogue outputs to tf32.
// B always pre-rounded.
// ---------------------------------------------------------------------------
#define GKDIM 1024
#define GNDIM 1024
#define NKT 64
#define A_STRIDE 20
#define B_STRIDE 136
#define A_BYTES (128 * A_STRIDE * 4)
#define B_BYTES (16 * B_STRIDE * 4)
#define STAGE_BYTES (A_BYTES + B_BYTES)
#define GSTAGES 4
#define GEMM_SMEM (GSTAGES * STAGE_BYTES)   // 75776

template <bool A_PRE, bool ROUND_OUT>
__device__ __forceinline__ void gemm_core(const float* __restrict__ A,
                                          const float* __restrict__ B,
                                          const float* __restrict__ bias,
                                          float* __restrict__ C,
                                          int m0, int n0, int useBias,
                                          char* dsmem)
{
    const int tid = threadIdx.x;
    const int wid = tid >> 5;
    const int lane = tid & 31;
    const int wm0 = (wid & 3) * 32;
    const int wn0 = (wid >> 2) * 64;
    const int qr = lane >> 2;
    const int qc = lane & 3;

    const uint32_t sbase = smem_to_u32(dsmem);

    float acc[2][8][4];
#pragma unroll
    for (int i = 0; i < 2; i++)
#pragma unroll
        for (int j = 0; j < 8; j++)
#pragma unroll
            for (int l = 0; l < 4; l++) acc[i][j][l] = 0.f;

    auto issue_stage = [&](int stage, int k0) {
        uint32_t aB = sbase + stage * STAGE_BYTES;
        uint32_t bB = aB + A_BYTES;
#pragma unroll
        for (int i = 0; i < 2; i++) {
            int idx = tid * 2 + i;
            int row = idx >> 2;
            int c4 = idx & 3;
            cp_async16(aB + row * (A_STRIDE * 4) + c4 * 16,
                       A + (size_t)(m0 + row) * GKDIM + k0 + c4 * 4);
            int krow = idx >> 5;
            int col = idx & 31;
            cp_async16(bB + krow * (B_STRIDE * 4) + col * 16,
                       B + (size_t)(k0 + krow) * GNDIM + n0 + col * 4);
        }
    };

    issue_stage(0, 0);
    CP_COMMIT();
    issue_stage(1, 16);
    CP_COMMIT();
    issue_stage(2, 32);
    CP_COMMIT();

    for (int kt = 0; kt < NKT; kt++) {
        int lt = kt + 3;
        if (lt < NKT) issue_stage(lt & 3, lt * 16);
        CP_COMMIT();
        CP_WAIT3();
        __syncthreads();

        const float* As = (const float*)(dsmem + (kt & 3) * STAGE_BYTES);
        const uint32_t* Asu = (const uint32_t*)As;
        const uint32_t* Bs = (const uint32_t*)(dsmem + (kt & 3) * STAGE_BYTES + A_BYTES);

#pragma unroll
        for (int ks = 0; ks < 2; ks++) {
            const int kb = ks * 8;
            uint32_t afr[2][4];
            uint32_t bfr[8][2];
#pragma unroll
            for (int mt = 0; mt < 2; mt++) {
                int mbase = wm0 + mt * 16;
                if (A_PRE) {
                    afr[mt][0] = Asu[(mbase + qr) * A_STRIDE + kb + qc];
                    afr[mt][1] = Asu[(mbase + qr + 8) * A_STRIDE + kb + qc];
                    afr[mt][2] = Asu[(mbase + qr) * A_STRIDE + kb + qc + 4];
                    afr[mt][3] = Asu[(mbase + qr + 8) * A_STRIDE + kb + qc + 4];
                } else {
                    afr[mt][0] = f2tf32(As[(mbase + qr) * A_STRIDE + kb + qc]);
                    afr[mt][1] = f2tf32(As[(mbase + qr + 8) * A_STRIDE + kb + qc]);
                    afr[mt][2] = f2tf32(As[(mbase + qr) * A_STRIDE + kb + qc + 4]);
                    afr[mt][3] = f2tf32(As[(mbase + qr + 8) * A_STRIDE + kb + qc + 4]);
                }
            }
#pragma unroll
            for (int nt = 0; nt < 8; nt++) {
                int nc = wn0 + nt * 8 + qr;
                bfr[nt][0] = Bs[(kb + qc) * B_STRIDE + nc];        // pre-rounded
                bfr[nt][1] = Bs[(kb + qc + 4) * B_STRIDE + nc];
            }
#pragma unroll
            for (int mt = 0; mt < 2; mt++)
#pragma unroll
                for (int nt = 0; nt < 8; nt++)
                    mma_tf32(acc[mt][nt], afr[mt], bfr[nt]);
        }
        __syncthreads();
    }

#pragma unroll
    for (int mt = 0; mt < 2; mt++) {
        int r0 = m0 + wm0 + mt * 16 + qr;
#pragma unroll
        for (int nt = 0; nt < 8; nt++) {
            int col = n0 + wn0 + nt * 8 + 2 * qc;
            float bx = 0.f, by = 0.f;
            if (useBias) {
                float2 bb = *(const float2*)(bias + col);
                bx = bb.x; by = bb.y;
            }
            float2 v0 = {acc[mt][nt][0] + bx, acc[mt][nt][1] + by};
            float2 v1 = {acc[mt][nt][2] + bx, acc[mt][nt][3] + by};
            if (ROUND_OUT) {
                v0.x = roundtf(v0.x); v0.y = roundtf(v0.y);
                v1.x = roundtf(v1.x); v1.y = roundtf(v1.y);
            }
            *(float2*)(C + (size_t)r0 * GNDIM + col) = v0;
            *(float2*)(C + (size_t)(r0 + 8) * GNDIM + col) = v1;
        }
    }
}

// Fused QKV: grid.x = 24 (3 weights x 8 N-tiles), grid.y = 64 (M-tiles)
__global__ __launch_bounds__(256)
void gemm_qkv_kernel(const float* __restrict__ x,
                     const float* __restrict__ Wq, const float* __restrict__ Wk,
                     const float* __restrict__ Wv,
                     float* __restrict__ q, float* __restrict__ k,
                     float* __restrict__ v)
{
    extern __shared__ char dsmem[];
    const int sel = blockIdx.x >> 3;
    const int n0 = (blockIdx.x & 7) * 128;
    const int m0 = blockIdx.y * 128;
    const float* B = (sel == 0) ? Wq : (sel == 1) ? Wk : Wv;
    float* C = (sel == 0) ? q : (sel == 1) ? k : v;
    gemm_core<true, true>(x, B, nullptr, C, m0, n0, 0, dsmem);
}

__global__ __launch_bounds__(256)
void gemm_tc_kernel(const float* __restrict__ A, const float* __restrict__ B,
                    const float* __restrict__ bias, float* __restrict__ C,
                    int useBias)
{
    extern __shared__ char dsmem[];
    gemm_core<true, false>(A, B, bias, C, blockIdx.y * 128, blockIdx.x * 128, useBias, dsmem);
}

// ---------------------------------------------------------------------------
// Flash attention (causal) with tf32 mma.sync. q/k/v pre-rounded in HBM.
// Br=128, Bc=64, 256 threads (8 warps). Single-buffered K/V (2 CTA/SM).
// Unified warp layout: warp w owns rows [16w,16w+16) in BOTH S and PV phases.
// Softmax fully in registers (quad shfl); P written once (pre-rounded) to the
// warp's private Ps rows; PV reads cvt-free. Split-group cp.async pipeline.
// ---------------------------------------------------------------------------
struct AttnSmem {
    float Qs[128][68];
    float Ks[64][68];
    float Vs[64][72];
    float Ps[128][68];
};   // ~71.7 KB

__global__ __launch_bounds__(256, 2)
void attn_mma_kernel(const float* __restrict__ q, const float* __restrict__ k,
                     const float* __restrict__ v, float* __restrict__ out)
{
    extern __shared__ char smem_raw[];
    AttnSmem& sm = *reinterpret_cast<AttnSmem*>(smem_raw);

    const int tid = threadIdx.x;
    const int wid = tid >> 5;
    const int lane = tid & 31;
    const int qr = lane >> 2;
    const int qc = lane & 3;
    const int q0 = (gridDim.x - 1 - blockIdx.x) * 128;   // heavy tiles first
    const int bh = blockIdx.y;
    const int b = bh >> 4;
    const int h = bh & 15;
    const int mbase = wid * 16;      // warp's row band (same for S and PV)

    const size_t base = (size_t)b * SEQ * DMODEL + (size_t)h * HDIM;

    // q pre-rounded; *0.125f is exponent-only -> still tf32-exact
    for (int idx = tid; idx < 2048; idx += 256) {
        int r = idx >> 4;
        int d4 = (idx & 15) << 2;
        float4 val = *(const float4*)(q + base + (size_t)(q0 + r) * DMODEL + d4);
        sm.Qs[r][d4 + 0] = val.x * 0.125f;
        sm.Qs[r][d4 + 1] = val.y * 0.125f;
        sm.Qs[r][d4 + 2] = val.z * 0.125f;
        sm.Qs[r][d4 + 3] = val.w * 0.125f;
    }

    auto load_k = [&](int k0) {
#pragma unroll
        for (int i = 0; i < 4; i++) {
            int idx = tid + i * 256;
            int c = idx >> 4;
            int d4 = (idx & 15) << 2;
            cp_async16(smem_to_u32(&sm.Ks[c][d4]),
                       k + base + (size_t)(k0 + c) * DMODEL + d4);
        }
    };
    auto load_v = [&](int k0) {
#pragma unroll
        for (int i = 0; i < 4; i++) {
            int idx = tid + i * 256;
            int c = idx >> 4;
            int d4 = (idx & 15) << 2;
            cp_async16(smem_to_u32(&sm.Vs[c][d4]),
                       v + base + (size_t)(k0 + c) * DMODEL + d4);
        }
    };

    float m_i0 = -INFINITY, m_i1 = -INFINITY;
    float l_i0 = 0.f, l_i1 = 0.f;

    float oacc[8][4];
#pragma unroll
    for (int nt = 0; nt < 8; nt++)
#pragma unroll
        for (int l = 0; l < 4; l++) oacc[nt][l] = 0.f;

    const int nkt = (q0 >> 6) + 2;

    // Pipeline prologue: groups in FIFO order {K0, V0}
    load_k(0);
    CP_COMMIT();
    load_v(0);
    CP_COMMIT();

    for (int kt = 0; kt < nkt; kt++) {
        const int k0 = kt * 64;

        CP_WAIT1();               // K(kt) ready; V(kt) may still be in flight
        __syncthreads();

        // ---- S = Q @ K^T (warp tile 16x64), plain LDS (pre-rounded) ----
        float sacc[8][4];
#pragma unroll
        for (int nt = 0; nt < 8; nt++)
#pragma unroll
            for (int l = 0; l < 4; l++) sacc[nt][l] = 0.f;

#pragma unroll
        for (int ks = 0; ks < 8; ks++) {
            const int kb = ks * 8;
            uint32_t afr[4];
            afr[0] = __float_as_uint(sm.Qs[mbase + qr][kb + qc]);
            afr[1] = __float_as_uint(sm.Qs[mbase + qr + 8][kb + qc]);
            afr[2] = __float_as_uint(sm.Qs[mbase + qr][kb + qc + 4]);
            afr[3] = __float_as_uint(sm.Qs[mbase + qr + 8][kb + qc + 4]);
            uint32_t bfr[8][2];
#pragma unroll
            for (int nt = 0; nt < 8; nt++) {
                int nc = nt * 8 + qr;
                bfr[nt][0] = __float_as_uint(sm.Ks[nc][kb + qc]);
                bfr[nt][1] = __float_as_uint(sm.Ks[nc][kb + qc + 4]);
            }
#pragma unroll
            for (int nt = 0; nt < 8; nt++)
                mma_tf32(sacc[nt], afr, bfr[nt]);
        }

        // ---- Register softmax (per-warp rows; quad shfl reductions) ----
        {
            // causal mask: col c valid iff c <= q0 + row - k0
            const int climit0 = q0 + mbase + qr - k0;      // row qr
            const int climit1 = climit0 + 8;               // row qr+8
            const bool nomask = (k0 + 63 <= q0 + mbase);   // warp-uniform
            if (!nomask) {
#pragma unroll
                for (int nt = 0; nt < 8; nt++) {
                    int c0 = nt * 8 + 2 * qc;
                    if (c0 > climit0)     sacc[nt][0] = -INFINITY;
                    if (c0 + 1 > climit0) sacc[nt][1] = -INFINITY;
                    if (c0 > climit1)     sacc[nt][2] = -INFINITY;
                    if (c0 + 1 > climit1) sacc[nt][3] = -INFINITY;
                }
            }
            float mx0 = -INFINITY, mx1 = -INFINITY;
#pragma unroll
            for (int nt = 0; nt < 8; nt++) {
                mx0 = fmaxf(mx0, fmaxf(sacc[nt][0], sacc[nt][1]));
                mx1 = fmaxf(mx1, fmaxf(sacc[nt][2], sacc[nt][3]));
            }
            mx0 = fmaxf(mx0, __shfl_xor_sync(0xffffffffu, mx0, 1));
            mx0 = fmaxf(mx0, __shfl_xor_sync(0xffffffffu, mx0, 2));
            mx1 = fmaxf(mx1, __shfl_xor_sync(0xffffffffu, mx1, 1));
            mx1 = fmaxf(mx1, __shfl_xor_sync(0xffffffffu, mx1, 2));

            float mnew0 = fmaxf(m_i0, mx0);
            float mnew1 = fmaxf(m_i1, mx1);
            float rs0 = __expf(m_i0 - mnew0);
            float rs1 = __expf(m_i1 - mnew1);
            m_i0 = mnew0;
            m_i1 = mnew1;

            float ls0 = 0.f, ls1 = 0.f;
#pragma unroll
            for (int nt = 0; nt < 8; nt++) {
                sacc[nt][0] = __expf(sacc[nt][0] - mnew0);
                sacc[nt][1] = __expf(sacc[nt][1] - mnew0);
                sacc[nt][2] = __expf(sacc[nt][2] - mnew1);
                sacc[nt][3] = __expf(sacc[nt][3] - mnew1);
                ls0 += sacc[nt][0] + sacc[nt][1];
                ls1 += sacc[nt][2] + sacc[nt][3];
            }
            ls0 += __shfl_xor_sync(0xffffffffu, ls0, 1);
            ls0 += __shfl_xor_sync(0xffffffffu, ls0, 2);
            ls1 += __shfl_xor_sync(0xffffffffu, ls1, 1);
            ls1 += __shfl_xor_sync(0xffffffffu, ls1, 2);
            l_i0 = l_i0 * rs0 + ls0;
            l_i1 = l_i1 * rs1 + ls1;

            // rescale O accumulator (per-thread, no smem)
#pragma unroll
            for (int nt = 0; nt < 8; nt++) {
                oacc[nt][0] *= rs0; oacc[nt][1] *= rs0;
                oacc[nt][2] *= rs1; oacc[nt][3] *= rs1;
            }

            // write P (pre-rounded) to the warp's OWN Ps rows
#pragma unroll
            for (int nt = 0; nt < 8; nt++) {
                int col = nt * 8 + 2 * qc;
                *(float2*)&sm.Ps[mbase + qr][col] =
                    make_float2(roundtf(sacc[nt][0]), roundtf(sacc[nt][1]));
                *(float2*)&sm.Ps[mbase + qr + 8][col] =
                    make_float2(roundtf(sacc[nt][2]), roundtf(sacc[nt][3]));
            }
        }
        __syncwarp();             // warp-local Ps visibility
        __syncthreads();          // all warps done reading Ks

        // Prefetch K(kt+1) — hidden behind PV
        if (kt + 1 < nkt) load_k(k0 + 64);
        CP_COMMIT();

        CP_WAIT1();               // V(kt) ready (K(kt+1) still pending)
        __syncthreads();          // V chunks visible to all threads

        // ---- O += P @ V (warp tile 16x64); all plain LDS ----
        {
            const uint32_t* Pu = (const uint32_t*)&sm.Ps[0][0];
            const uint32_t* Vu = (const uint32_t*)&sm.Vs[0][0];
#pragma unroll
            for (int ks = 0; ks < 8; ks++) {
                const int kb = ks * 8;
                uint32_t afr[4];
                afr[0] = Pu[(mbase + qr) * 68 + kb + qc];
                afr[1] = Pu[(mbase + qr + 8) * 68 + kb + qc];
                afr[2] = Pu[(mbase + qr) * 68 + kb + qc + 4];
                afr[3] = Pu[(mbase + qr + 8) * 68 + kb + qc + 4];
                uint32_t bfr[8][2];
#pragma unroll
                for (int nt = 0; nt < 8; nt++) {
                    int nc = nt * 8 + qr;
                    bfr[nt][0] = Vu[(kb + qc) * 72 + nc];
                    bfr[nt][1] = Vu[(kb + qc + 4) * 72 + nc];
                }
#pragma unroll
                for (int nt = 0; nt < 8; nt++)
                    mma_tf32(oacc[nt], afr, bfr[nt]);
            }
        }
        __syncthreads();          // all warps done reading Vs(kt)

        // Issue V(kt+1) — hidden behind next S-phase
        if (kt + 1 < nkt) load_v(k0 + 64);
        CP_COMMIT();
    }

    // Final normalization (per-thread l_i) + round for O-proj A_PRE
    {
        float inv0 = 1.f / l_i0;
        float inv1 = 1.f / l_i1;
        size_t r0 = base + (size_t)(q0 + mbase + qr) * DMODEL;
        size_t r1 = base + (size_t)(q0 + mbase + qr + 8) * DMODEL;
#pragma unroll
        for (int nt = 0; nt < 8; nt++) {
            int col = nt * 8 + 2 * qc;
            *(float2*)(out + r0 + col) =
                make_float2(roundtf(oacc[nt][0] * inv0), roundtf(oacc[nt][1] * inv0));
            *(float2*)(out + r1 + col) =
                make_float2(roundtf(oacc[nt][2] * inv1), roundtf(oacc[nt][3] * inv1));
        }
    }
}

// ---------------------------------------------------------------------------
// Launch
// ---------------------------------------------------------------------------
extern "C" void kernel_launch(void* const* d_in, const int* in_sizes, int n_in,
                              void* d_out, int out_size)
{
    const float* x  = (const float*)d_in[0];
    const float* Wq = (const float*)d_in[1];
    const float* Wk = (const float*)d_in[2];
    const float* Wv = (const float*)d_in[3];
    const float* Wo = (const float*)d_in[4];
    const float* bo = (const float*)d_in[5];
    float* out = (float*)d_out;

    float *qp, *kp, *vp, *ap, *xr, *wr;
    cudaGetSymbolAddress((void**)&qp, g_q);
    cudaGetSymbolAddress((void**)&kp, g_k);
    cudaGetSymbolAddress((void**)&vp, g_v);
    cudaGetSymbolAddress((void**)&ap, g_attn);
    cudaGetSymbolAddress((void**)&xr, g_xr);
    cudaGetSymbolAddress((void**)&wr, g_wr);
    float* wrq = wr;
    float* wro = wr + 3 * DMODEL * DMODEL;

    cudaFuncSetAttribute(gemm_qkv_kernel, cudaFuncAttributeMaxDynamicSharedMemorySize, GEMM_SMEM);
    cudaFuncSetAttribute(gemm_tc_kernel, cudaFuncAttributeMaxDynamicSharedMemorySize, GEMM_SMEM);
    cudaFuncSetAttribute(attn_mma_kernel, cudaFuncAttributeMaxDynamicSharedMemorySize,
                         (int)sizeof(AttnSmem));

    // Pre-round x and weights (grid-strided, 4 float4/thread)
    const int XN4 = MTOT * DMODEL / 4;
    const int WN4 = DMODEL * DMODEL / 4;
    round_x_kernel<<<XN4 / (256 * 4), 256>>>((const float4*)x, (float4*)xr, XN4);
    dim3 wgrid(WN4 / (256 * 4), 4);
    round_w_kernel<<<wgrid, 256>>>((const float4*)Wq, (const float4*)Wk,
                                   (const float4*)Wv, (const float4*)Wo,
                                   (float4*)wr, WN4);

    // Fused QKV projections (zero-cvt inner loop, rounded outputs)
    dim3 qkvgrid(24, MTOT / 128);
    gemm_qkv_kernel<<<qkvgrid, 256, GEMM_SMEM>>>(xr, wrq, wrq + WN4 * 4, wrq + 2 * WN4 * 4,
                                                 qp, kp, vp);

    // Causal flash attention (register softmax, unified warp layout)
    dim3 agrid(SEQ / 128, BATCH * NHEADS);
    attn_mma_kernel<<<agrid, 256, sizeof(AttnSmem)>>>(qp, kp, vp, ap);

    // Output projection + bias (A pre-rounded by attn epilogue)
    dim3 ggrid(GNDIM / 128, MTOT / 128);
    gemm_tc_kernel<<<ggrid, 256, GEMM_SMEM>>>(ap, wro, bo, out, 1);
}

// round 16
// speedup vs baseline: 1.7549x; 1.0279x over previous
#include <cuda_runtime.h>
#include <cuda_bf16.h>
#include <math.h>
#include <stdint.h>

// Problem constants
#define BATCH 4
#define SEQ 2048
#define DMODEL 1024
#define NHEADS 16
#define HDIM 64
#define MTOT (BATCH * SEQ)          // 8192 rows

// ---------------------------------------------------------------------------
// Scratch (device globals: allocation-free, graph-safe)
// ---------------------------------------------------------------------------
__device__ float g_q[MTOT * DMODEL];
__device__ float g_k[MTOT * DMODEL];
__device__ float g_v[MTOT * DMODEL];
__device__ float g_attn[MTOT * DMODEL];
__device__ float g_xr[MTOT * DMODEL];        // tf32-rounded x
__device__ float g_wr[4][DMODEL * DMODEL];   // tf32-rounded Wq,Wk,Wv,Wo

// ---------------------------------------------------------------------------
// Helpers
// ---------------------------------------------------------------------------
__device__ __forceinline__ uint32_t smem_to_u32(const void* p) {
    uint32_t a;
    asm("{ .reg .u64 t; cvta.to.shared.u64 t, %1; cvt.u32.u64 %0, t; }"
        : "=r"(a) : "l"(p));
    return a;
}
__device__ __forceinline__ void cp_async16(uint32_t dst, const void* src) {
    asm volatile("cp.async.cg.shared.global [%0], [%1], 16;" :: "r"(dst), "l"(src));
}
#define CP_COMMIT() asm volatile("cp.async.commit_group;" ::: "memory")
#define CP_WAIT0()  asm volatile("cp.async.wait_group 0;" ::: "memory")
#define CP_WAIT2()  asm volatile("cp.async.wait_group 2;" ::: "memory")

__device__ __forceinline__ uint32_t f2tf32(float f) {
    uint32_t r;
    asm("cvt.rna.tf32.f32 %0, %1;" : "=r"(r) : "f"(f));
    return r;
}
__device__ __forceinline__ float roundtf(float f) {
    return __uint_as_float(f2tf32(f));
}
__device__ __forceinline__ void mma_tf32(float* c, const uint32_t* a, const uint32_t* b) {
    asm volatile(
        "mma.sync.aligned.m16n8k8.row.col.f32.tf32.tf32.f32 "
        "{%0,%1,%2,%3}, {%4,%5,%6,%7}, {%8,%9}, {%0,%1,%2,%3};"
        : "+f"(c[0]), "+f"(c[1]), "+f"(c[2]), "+f"(c[3])
        : "r"(a[0]), "r"(a[1]), "r"(a[2]), "r"(a[3]), "r"(b[0]), "r"(b[1]));
}

// ---------------------------------------------------------------------------
// Pre-pass: round fp32 -> tf32 bit pattern. Grid-strided, 4 float4/thread.
// ---------------------------------------------------------------------------
__global__ __launch_bounds__(256)
void round_x_kernel(const float4* __restrict__ in, float4* __restrict__ out, int n4)
{
    int stride = gridDim.x * 256;
    for (int i = blockIdx.x * 256 + threadIdx.x; i < n4; i += stride) {
        float4 v = in[i];
        v.x = roundtf(v.x);
        v.y = roundtf(v.y);
        v.z = roundtf(v.z);
        v.w = roundtf(v.w);
        out[i] = v;
    }
}

__global__ __launch_bounds__(256)
void round_w_kernel(const float4* __restrict__ w0, const float4* __restrict__ w1,
                    const float4* __restrict__ w2, const float4* __restrict__ w3,
                    float4* __restrict__ out, int n4)
{
    const float4* in = (blockIdx.y == 0) ? w0 : (blockIdx.y == 1) ? w1
                     : (blockIdx.y == 2) ? w2 : w3;
    float4* dst = out + (size_t)blockIdx.y * n4;
    int stride = gridDim.x * 256;
    for (int i = blockIdx.x * 256 + threadIdx.x; i < n4; i += stride) {
        float4 v = in[i];
        v.x = roundtf(v.x);
        v.y = roundtf(v.y);
        v.z = roundtf(v.z);
        v.w = roundtf(v.w);
        dst[i] = v;
    }
}

// ---------------------------------------------------------------------------
// tf32 mma.sync GEMM core (BM=128 BN=128 BK=16, 256 thr, 4-stage cp.async).
// Single barrier per k-tile: [WAIT2; barrier; issue(kt+3); commit; mma].
// The top barrier is after mma(kt-1) in program order -> safely guards the
// stage (kt+3)&3 == (kt-1)&3 being overwritten.
// ---------------------------------------------------------------------------
#define GKDIM 1024
#define GNDIM 1024
#define NKT 64
#define A_STRIDE 20
#define B_STRIDE 136
#define A_BYTES (128 * A_STRIDE * 4)
#define B_BYTES (16 * B_STRIDE * 4)
#define STAGE_BYTES (A_BYTES + B_BYTES)
#define GSTAGES 4
#define GEMM_SMEM (GSTAGES * STAGE_BYTES)   // 75776

template <bool A_PRE, bool ROUND_OUT>
__device__ __forceinline__ void gemm_core(const float* __restrict__ A,
                                          const float* __restrict__ B,
                                          const float* __restrict__ bias,
                                          float* __restrict__ C,
                                          int m0, int n0, int useBias,
                                          char* dsmem)
{
    const int tid = threadIdx.x;
    const int wid = tid >> 5;
    const int lane = tid & 31;
    const int wm0 = (wid & 3) * 32;
    const int wn0 = (wid >> 2) * 64;
    const int qr = lane >> 2;
    const int qc = lane & 3;

    const uint32_t sbase = smem_to_u32(dsmem);

    float acc[2][8][4];
#pragma unroll
    for (int i = 0; i < 2; i++)
#pragma unroll
        for (int j = 0; j < 8; j++)
#pragma unroll
            for (int l = 0; l < 4; l++) acc[i][j][l] = 0.f;

    auto issue_stage = [&](int stage, int k0) {
        uint32_t aB = sbase + stage * STAGE_BYTES;
        uint32_t bB = aB + A_BYTES;
#pragma unroll
        for (int i = 0; i < 2; i++) {
            int idx = tid * 2 + i;
            int row = idx >> 2;
            int c4 = idx & 3;
            cp_async16(aB + row * (A_STRIDE * 4) + c4 * 16,
                       A + (size_t)(m0 + row) * GKDIM + k0 + c4 * 4);
            int krow = idx >> 5;
            int col = idx & 31;
            cp_async16(bB + krow * (B_STRIDE * 4) + col * 16,
                       B + (size_t)(k0 + krow) * GNDIM + n0 + col * 4);
        }
    };

    issue_stage(0, 0);
    CP_COMMIT();
    issue_stage(1, 16);
    CP_COMMIT();
    issue_stage(2, 32);
    CP_COMMIT();

    for (int kt = 0; kt < NKT; kt++) {
        CP_WAIT2();               // retire group kt (3 pending -> <=2)
        __syncthreads();          // stage kt data visible; mma(kt-1) done everywhere

        int lt = kt + 3;
        if (lt < NKT) issue_stage(lt & 3, lt * 16);
        CP_COMMIT();              // always: keep group accounting exact

        const float* As = (const float*)(dsmem + (kt & 3) * STAGE_BYTES);
        const uint32_t* Asu = (const uint32_t*)As;
        const uint32_t* Bs = (const uint32_t*)(dsmem + (kt & 3) * STAGE_BYTES + A_BYTES);

#pragma unroll
        for (int ks = 0; ks < 2; ks++) {
            const int kb = ks * 8;
            uint32_t afr[2][4];
            uint32_t bfr[8][2];
#pragma unroll
            for (int mt = 0; mt < 2; mt++) {
                int mbase = wm0 + mt * 16;
                if (A_PRE) {
                    afr[mt][0] = Asu[(mbase + qr) * A_STRIDE + kb + qc];
                    afr[mt][1] = Asu[(mbase + qr + 8) * A_STRIDE + kb + qc];
                    afr[mt][2] = Asu[(mbase + qr) * A_STRIDE + kb + qc + 4];
                    afr[mt][3] = Asu[(mbase + qr + 8) * A_STRIDE + kb + qc + 4];
                } else {
                    afr[mt][0] = f2tf32(As[(mbase + qr) * A_STRIDE + kb + qc]);
                    afr[mt][1] = f2tf32(As[(mbase + qr + 8) * A_STRIDE + kb + qc]);
                    afr[mt][2] = f2tf32(As[(mbase + qr) * A_STRIDE + kb + qc + 4]);
                    afr[mt][3] = f2tf32(As[(mbase + qr + 8) * A_STRIDE + kb + qc + 4]);
                }
            }
#pragma unroll
            for (int nt = 0; nt < 8; nt++) {
                int nc = wn0 + nt * 8 + qr;
                bfr[nt][0] = Bs[(kb + qc) * B_STRIDE + nc];        // pre-rounded
                bfr[nt][1] = Bs[(kb + qc + 4) * B_STRIDE + nc];
            }
#pragma unroll
            for (int mt = 0; mt < 2; mt++)
#pragma unroll
                for (int nt = 0; nt < 8; nt++)
                    mma_tf32(acc[mt][nt], afr[mt], bfr[nt]);
        }
    }

#pragma unroll
    for (int mt = 0; mt < 2; mt++) {
        int r0 = m0 + wm0 + mt * 16 + qr;
#pragma unroll
        for (int nt = 0; nt < 8; nt++) {
            int col = n0 + wn0 + nt * 8 + 2 * qc;
            float bx = 0.f, by = 0.f;
            if (useBias) {
                float2 bb = *(const float2*)(bias + col);
                bx = bb.x; by = bb.y;
            }
            float2 v0 = {acc[mt][nt][0] + bx, acc[mt][nt][1] + by};
            float2 v1 = {acc[mt][nt][2] + bx, acc[mt][nt][3] + by};
            if (ROUND_OUT) {
                v0.x = roundtf(v0.x); v0.y = roundtf(v0.y);
                v1.x = roundtf(v1.x); v1.y = roundtf(v1.y);
            }
            *(float2*)(C + (size_t)r0 * GNDIM + col) = v0;
            *(float2*)(C + (size_t)(r0 + 8) * GNDIM + col) = v1;
        }
    }
}

// Fused QKV: grid.x = 24 (3 weights x 8 N-tiles), grid.y = 64 (M-tiles)
__global__ __launch_bounds__(256)
void gemm_qkv_kernel(const float* __restrict__ x,
                     const float* __restrict__ Wq, const float* __restrict__ Wk,
                     const float* __restrict__ Wv,
                     float* __restrict__ q, float* __restrict__ k,
                     float* __restrict__ v)
{
    extern __shared__ char dsmem[];
    const int sel = blockIdx.x >> 3;
    const int n0 = (blockIdx.x & 7) * 128;
    const int m0 = blockIdx.y * 128;
    const float* B = (sel == 0) ? Wq : (sel == 1) ? Wk : Wv;
    float* C = (sel == 0) ? q : (sel == 1) ? k : v;
    gemm_core<true, true>(x, B, nullptr, C, m0, n0, 0, dsmem);
}

__global__ __launch_bounds__(256)
void gemm_tc_kernel(const float* __restrict__ A, const float* __restrict__ B,
                    const float* __restrict__ bias, float* __restrict__ C,
                    int useBias)
{
    extern __shared__ char dsmem[];
    gemm_core<true, false>(A, B, bias, C, blockIdx.y * 128, blockIdx.x * 128, useBias, dsmem);
}

// ---------------------------------------------------------------------------
// Flash attention (causal) with tf32 mma.sync. q/k/v pre-rounded in HBM.
// Br=128, Bc=64, 256 threads (8 warps). DOUBLE-buffered K/V (2 CTA/SM).
// P never touches smem: S-accumulator fragments are redistributed into PV
// A-fragment layout via quad shfl. ONE barrier + ONE wait per K-tile;
// K/V(kt+1) issued a full tile ahead.
// ---------------------------------------------------------------------------
struct AttnSmem {
    float Qs[128][68];       // 34816 B
    float Ks[2][64][68];     // 34816 B
    float Vs[2][64][72];     // 36864 B
};   // 106496 B -> 2 CTAs/SM

__global__ __launch_bounds__(256, 2)
void attn_mma_kernel(const float* __restrict__ q, const float* __restrict__ k,
                     const float* __restrict__ v, float* __restrict__ out)
{
    extern __shared__ char smem_raw[];
    AttnSmem& sm = *reinterpret_cast<AttnSmem*>(smem_raw);

    const int tid = threadIdx.x;
    const int wid = tid >> 5;
    const int lane = tid & 31;
    const int qr = lane >> 2;
    const int qc = lane & 3;
    const int q0 = (gridDim.x - 1 - blockIdx.x) * 128;   // heavy tiles first
    const int bh = blockIdx.y;
    const int b = bh >> 4;
    const int h = bh & 15;
    const int mbase = wid * 16;      // warp's row band (same for S and PV)
    const int ls0 = (lane & ~3) | (qc >> 1);   // shfl src for PV a0/a1
    const int ls1 = ls0 + 2;                   // shfl src for PV a2/a3
    const int bsel = qc & 1;

    const size_t base = (size_t)b * SEQ * DMODEL + (size_t)h * HDIM;

    // q pre-rounded; *0.125f is exponent-only -> still tf32-exact
    for (int idx = tid; idx < 2048; idx += 256) {
        int r = idx >> 4;
        int d4 = (idx & 15) << 2;
        float4 val = *(const float4*)(q + base + (size_t)(q0 + r) * DMODEL + d4);
        sm.Qs[r][d4 + 0] = val.x * 0.125f;
        sm.Qs[r][d4 + 1] = val.y * 0.125f;
        sm.Qs[r][d4 + 2] = val.z * 0.125f;
        sm.Qs[r][d4 + 3] = val.w * 0.125f;
    }

    auto load_kv = [&](int buf, int k0) {
#pragma unroll
        for (int i = 0; i < 4; i++) {
            int idx = tid + i * 256;
            int c = idx >> 4;
            int d4 = (idx & 15) << 2;
            cp_async16(smem_to_u32(&sm.Ks[buf][c][d4]),
                       k + base + (size_t)(k0 + c) * DMODEL + d4);
            cp_async16(smem_to_u32(&sm.Vs[buf][c][d4]),
                       v + base + (size_t)(k0 + c) * DMODEL + d4);
        }
    };

    float m_i0 = -INFINITY, m_i1 = -INFINITY;
    float l_i0 = 0.f, l_i1 = 0.f;

    float oacc[8][4];
#pragma unroll
    for (int nt = 0; nt < 8; nt++)
#pragma unroll
        for (int l = 0; l < 4; l++) oacc[nt][l] = 0.f;

    const int nkt = (q0 >> 6) + 2;

    load_kv(0, 0);
    CP_COMMIT();

    for (int kt = 0; kt < nkt; kt++) {
        const int k0 = kt * 64;
        const int buf = kt & 1;

        CP_WAIT0();               // K(kt),V(kt) landed (issued a full tile ago)
        __syncthreads();          // data visible; all warps done with buf^1 (PV kt-1)

        // Prefetch next tile into the other buffer — hidden behind this tile
        if (kt + 1 < nkt) {
            load_kv(buf ^ 1, k0 + 64);
            CP_COMMIT();
        }

        // ---- S = Q @ K^T (warp tile 16x64), plain LDS (pre-rounded) ----
        float sacc[8][4];
#pragma unroll
        for (int nt = 0; nt < 8; nt++)
#pragma unroll
            for (int l = 0; l < 4; l++) sacc[nt][l] = 0.f;

#pragma unroll
        for (int ks = 0; ks < 8; ks++) {
            const int kb = ks * 8;
            uint32_t afr[4];
            afr[0] = __float_as_uint(sm.Qs[mbase + qr][kb + qc]);
            afr[1] = __float_as_uint(sm.Qs[mbase + qr + 8][kb + qc]);
            afr[2] = __float_as_uint(sm.Qs[mbase + qr][kb + qc + 4]);
            afr[3] = __float_as_uint(sm.Qs[mbase + qr + 8][kb + qc + 4]);
            uint32_t bfr[8][2];
#pragma unroll
            for (int nt = 0; nt < 8; nt++) {
                int nc = nt * 8 + qr;
                bfr[nt][0] = __float_as_uint(sm.Ks[buf][nc][kb + qc]);
                bfr[nt][1] = __float_as_uint(sm.Ks[buf][nc][kb + qc + 4]);
            }
#pragma unroll
            for (int nt = 0; nt < 8; nt++)
                mma_tf32(sacc[nt], afr, bfr[nt]);
        }

        // ---- Register softmax (per-warp rows; quad shfl reductions) ----
        {
            const int climit0 = q0 + mbase + qr - k0;      // row qr
            const int climit1 = climit0 + 8;               // row qr+8
            const bool nomask = (k0 + 63 <= q0 + mbase);   // warp-uniform
            if (!nomask) {
#pragma unroll
                for (int nt = 0; nt < 8; nt++) {
                    int c0 = nt * 8 + 2 * qc;
                    if (c0 > climit0)     sacc[nt][0] = -INFINITY;
                    if (c0 + 1 > climit0) sacc[nt][1] = -INFINITY;
                    if (c0 > climit1)     sacc[nt][2] = -INFINITY;
                    if (c0 + 1 > climit1) sacc[nt][3] = -INFINITY;
                }
            }
            float mx0 = -INFINITY, mx1 = -INFINITY;
#pragma unroll
            for (int nt = 0; nt < 8; nt++) {
                mx0 = fmaxf(mx0, fmaxf(sacc[nt][0], sacc[nt][1]));
                mx1 = fmaxf(mx1, fmaxf(sacc[nt][2], sacc[nt][3]));
            }
            mx0 = fmaxf(mx0, __shfl_xor_sync(0xffffffffu, mx0, 1));
            mx0 = fmaxf(mx0, __shfl_xor_sync(0xffffffffu, mx0, 2));
            mx1 = fmaxf(mx1, __shfl_xor_sync(0xffffffffu, mx1, 1));
            mx1 = fmaxf(mx1, __shfl_xor_sync(0xffffffffu, mx1, 2));

            float mnew0 = fmaxf(m_i0, mx0);
            float mnew1 = fmaxf(m_i1, mx1);
            float rs0 = __expf(m_i0 - mnew0);
            float rs1 = __expf(m_i1 - mnew1);
            m_i0 = mnew0;
            m_i1 = mnew1;

            float ls0s = 0.f, ls1s = 0.f;
#pragma unroll
            for (int nt = 0; nt < 8; nt++) {
                float e0 = __expf(sacc[nt][0] - mnew0);
                float e1 = __expf(sacc[nt][1] - mnew0);
                float e2 = __expf(sacc[nt][2] - mnew1);
                float e3 = __expf(sacc[nt][3] - mnew1);
                ls0s += e0 + e1;
                ls1s += e2 + e3;
                sacc[nt][0] = roundtf(e0);
                sacc[nt][1] = roundtf(e1);
                sacc[nt][2] = roundtf(e2);
                sacc[nt][3] = roundtf(e3);
            }
            ls0s += __shfl_xor_sync(0xffffffffu, ls0s, 1);
            ls0s += __shfl_xor_sync(0xffffffffu, ls0s, 2);
            ls1s += __shfl_xor_sync(0xffffffffu, ls1s, 1);
            ls1s += __shfl_xor_sync(0xffffffffu, ls1s, 2);
            l_i0 = l_i0 * rs0 + ls0s;
            l_i1 = l_i1 * rs1 + ls1s;

#pragma unroll
            for (int nt = 0; nt < 8; nt++) {
                oacc[nt][0] *= rs0; oacc[nt][1] *= rs0;
                oacc[nt][2] *= rs1; oacc[nt][3] *= rs1;
            }
        }

        // ---- O += P @ V; P fragments via quad shfl (no smem) ----
        {
            const uint32_t* Vu = (const uint32_t*)&sm.Vs[buf][0][0];
#pragma unroll
            for (int ks = 0; ks < 8; ks++) {
                const int kb = ks * 8;
                float e0 = __shfl_sync(0xffffffffu, sacc[ks][0], ls0);
                float e1 = __shfl_sync(0xffffffffu, sacc[ks][1], ls0);
                float e2 = __shfl_sync(0xffffffffu, sacc[ks][2], ls0);
                float e3 = __shfl_sync(0xffffffffu, sacc[ks][3], ls0);
                float g0 = __shfl_sync(0xffffffffu, sacc[ks][0], ls1);
                float g1 = __shfl_sync(0xffffffffu, sacc[ks][1], ls1);
                float g2 = __shfl_sync(0xffffffffu, sacc[ks][2], ls1);
                float g3 = __shfl_sync(0xffffffffu, sacc[ks][3], ls1);
                uint32_t afr[4];
                afr[0] = __float_as_uint(bsel ? e1 : e0);   // row qr,   col kb+qc
                afr[1] = __float_as_uint(bsel ? e3 : e2);   // row qr+8, col kb+qc
                afr[2] = __float_as_uint(bsel ? g1 : g0);   // row qr,   col kb+qc+4
                afr[3] = __float_as_uint(bsel ? g3 : g2);   // row qr+8, col kb+qc+4
                uint32_t bfr[8][2];
#pragma unroll
                for (int nt = 0; nt < 8; nt++) {
                    int nc = nt * 8 + qr;
                    bfr[nt][0] = Vu[(kb + qc) * 72 + nc];
                    bfr[nt][1] = Vu[(kb + qc + 4) * 72 + nc];
                }
#pragma unroll
                for (int nt = 0; nt < 8; nt++)
                    mma_tf32(oacc[nt], afr, bfr[nt]);
            }
        }
        // no trailing barrier: next iteration's barrier (after its WAIT0)
        // guards buffer reuse — issue of buf^1 happens after that barrier.
    }

    // Final normalization (per-thread l_i) + round for O-proj A_PRE
    {
        float inv0 = 1.f / l_i0;
        float inv1 = 1.f / l_i1;
        size_t r0 = base + (size_t)(q0 + mbase + qr) * DMODEL;
        size_t r1 = base + (size_t)(q0 + mbase + qr + 8) * DMODEL;
#pragma unroll
        for (int nt = 0; nt < 8; nt++) {
            int col = nt * 8 + 2 * qc;
            *(float2*)(out + r0 + col) =
                make_float2(roundtf(oacc[nt][0] * inv0), roundtf(oacc[nt][1] * inv0));
            *(float2*)(out + r1 + col) =
                make_float2(roundtf(oacc[nt][2] * inv1), roundtf(oacc[nt][3] * inv1));
        }
    }
}

// ---------------------------------------------------------------------------
// Launch
// ---------------------------------------------------------------------------
extern "C" void kernel_launch(void* const* d_in, const int* in_sizes, int n_in,
                              void* d_out, int out_size)
{
    const float* x  = (const float*)d_in[0];
    const float* Wq = (const float*)d_in[1];
    const float* Wk = (const float*)d_in[2];
    const float* Wv = (const float*)d_in[3];
    const float* Wo = (const float*)d_in[4];
    const float* bo = (const float*)d_in[5];
    float* out = (float*)d_out;

    float *qp, *kp, *vp, *ap, *xr, *wr;
    cudaGetSymbolAddress((void**)&qp, g_q);
    cudaGetSymbolAddress((void**)&kp, g_k);
    cudaGetSymbolAddress((void**)&vp, g_v);
    cudaGetSymbolAddress((void**)&ap, g_attn);
    cudaGetSymbolAddress((void**)&xr, g_xr);
    cudaGetSymbolAddress((void**)&wr, g_wr);
    float* wrq = wr;
    float* wro = wr + 3 * DMODEL * DMODEL;

    cudaFuncSetAttribute(gemm_qkv_kernel, cudaFuncAttributeMaxDynamicSharedMemorySize, GEMM_SMEM);
    cudaFuncSetAttribute(gemm_tc_kernel, cudaFuncAttributeMaxDynamicSharedMemorySize, GEMM_SMEM);
    cudaFuncSetAttribute(attn_mma_kernel, cudaFuncAttributeMaxDynamicSharedMemorySize,
                         (int)sizeof(AttnSmem));

    // Pre-round x and weights (grid-strided, 4 float4/thread)
    const int XN4 = MTOT * DMODEL / 4;
    const int WN4 = DMODEL * DMODEL / 4;
    round_x_kernel<<<XN4 / (256 * 4), 256>>>((const float4*)x, (float4*)xr, XN4);
    dim3 wgrid(WN4 / (256 * 4), 4);
    round_w_kernel<<<wgrid, 256>>>((const float4*)Wq, (const float4*)Wk,
                                   (const float4*)Wv, (const float4*)Wo,
                                   (float4*)wr, WN4);

    // Fused QKV projections (zero-cvt inner loop, rounded outputs)
    dim3 qkvgrid(24, MTOT / 128);
    gemm_qkv_kernel<<<qkvgrid, 256, GEMM_SMEM>>>(xr, wrq, wrq + WN4 * 4, wrq + 2 * WN4 * 4,
                                                 qp, kp, vp);

    // Causal flash attention (register softmax + shfl-P, double-buffered K/V)
    dim3 agrid(SEQ / 128, BATCH * NHEADS);
    attn_mma_kernel<<<agrid, 256, sizeof(AttnSmem)>>>(qp, kp, vp, ap);

    // Output projection + bias (A pre-rounded by attn epilogue)
    dim3 ggrid(GNDIM / 128, MTOT / 128);
    gemm_tc_kernel<<<ggrid, 256, GEMM_SMEM>>>(ap, wro, bo, out, 1);
}